// round 12
// baseline (speedup 1.0000x reference)
#include <cuda_runtime.h>
#include <stdint.h>
#include <math.h>

#define Db 256
#define NB 32
#define NTOK 4096
#define NS 8
#define HMLP 512
#define NBLK 4
#define ROWS (NB * NS)
#define EPS_LN 1e-3f
#define EPS_ATTN 1e-8f
#define ATT_SCALE 0.0625f

// ---------------- static scratch ----------------
__device__ float g_slots[ROWS * Db];
__device__ float g_qk[ROWS * Db];
__device__ float g_qb[ROWS];
__device__ float g_partU[NB * NBLK * NS * Db];
__device__ float g_partZ[NB * NBLK * NS];
__device__ float g_Wqk[Db * Db];         // [k][o] k-major (lnqk + tail H)
__device__ float g_wcombT[Db * 3 * Db];  // [k][o] k-major (W_ih@Wv)^T
__device__ float g_WhhT[Db * 3 * Db];    // [k][o]
__device__ float g_W1T[Db * HMLP];       // [k][o]
__device__ float g_W2T[HMLP * Db];       // [k][o]
__device__ float g_bcomb[3 * Db];
__device__ float g_wqbk[Db];
__device__ float g_bqk[Db];
__device__ float g_bqbk[1];

// ---------------- f32x2 packed helpers (sm_103a) ----------------
union F2U { float2 f; unsigned long long u; };
__device__ __forceinline__ float2 f2fma(float2 a, float2 b, float2 c) {
    F2U A, B, C, D;
    A.f = a; B.f = b; C.f = c;
    asm("fma.rn.f32x2 %0, %1, %2, %3;" : "=l"(D.u) : "l"(A.u), "l"(B.u), "l"(C.u));
    return D.f;
}
__device__ __forceinline__ float2 f2mul(float2 a, float2 b) {
    F2U A, B, D;
    A.f = a; B.f = b;
    asm("mul.rn.f32x2 %0, %1, %2;" : "=l"(D.u) : "l"(A.u), "l"(B.u));
    return D.f;
}
__device__ __forceinline__ float2 f2add(float2 a, float2 b) {
    F2U A, B, D;
    A.f = a; B.f = b;
    asm("add.rn.f32x2 %0, %1, %2;" : "=l"(D.u) : "l"(A.u), "l"(B.u));
    return D.f;
}

__device__ __forceinline__ void cp16(uint32_t dst, const void* src) {
    asm volatile("cp.async.ca.shared.global [%0], [%1], 16;" :: "r"(dst), "l"(src) : "memory");
}

// ---------------- prep ----------------
__global__ void prep_all_kernel(const float* __restrict__ slots,
                                const float* __restrict__ W_ih, const float* __restrict__ b_ih,
                                const float* __restrict__ bv, const float* __restrict__ Wq,
                                const float* __restrict__ bq, const float* __restrict__ bk,
                                const float* __restrict__ Wk) {
    int blk = blockIdx.x, t = threadIdx.x;
    if (blk >= 5) {
        int i = (blk - 5) * 256 + t;
        g_slots[i] = slots[i];
        return;
    }
    if (blk < 3) {
        int o = blk * Db + t;
        float acc = b_ih[o];
        for (int d = 0; d < Db; d++) acc = fmaf(W_ih[o * Db + d], bv[d], acc);
        g_bcomb[o] = acc;
    } else if (blk == 3) {
        float acc = 0.f;
        for (int c = 0; c < Db; c++) acc = fmaf(Wq[c * Db + t], bk[c], acc);
        g_wqbk[t] = acc;
        __shared__ float red[Db];
        red[t] = bq[t] * bk[t];
        __syncthreads();
        for (int s = 128; s > 0; s >>= 1) {
            if (t < s) red[t] += red[t + s];
            __syncthreads();
        }
        if (t == 0) g_bqbk[0] = red[0];
    } else {
        float acc = 0.f;
        for (int c = 0; c < Db; c++) acc = fmaf(bq[c], Wk[c * Db + t], acc);
        g_bqk[t] = acc;
    }
}

// ---------------- 32x32 tiled transpose: dst[c][r] = src[r][c] ----------------
__global__ void transpose_kernel(const float* __restrict__ src, float* __restrict__ dst,
                                 int R, int C) {
    __shared__ float t[32][33];
    const int rb = blockIdx.y * 32, cb = blockIdx.x * 32;
    const int tx = threadIdx.x & 31, ty = threadIdx.x >> 5;
#pragma unroll
    for (int i = 0; i < 32; i += 8)
        t[ty + i][tx] = src[(size_t)(rb + ty + i) * C + cb + tx];
    __syncthreads();
#pragma unroll
    for (int i = 0; i < 32; i += 8)
        dst[(size_t)(cb + ty + i) * R + rb + tx] = t[tx][ty + i];
}

// ---------------- ping-pong GEMM (prep only): 32x64 tile, K-step 32 ----------------
// TRANSA: A is [K][R]. TRANSB: B is [O][K] (C=A@B^T), else [K][O].
template <int TRANSA, int TRANSB>
__global__ void __launch_bounds__(256, 2)
gemmp_kernel(const float* __restrict__ A, const float* __restrict__ Bm,
             float* __restrict__ C, int R, int O, int K) {
    __shared__ float As[2][32][33];
    __shared__ float Bs[2][32][68];
    const int r0 = blockIdx.x * 32;
    const int o0 = blockIdx.y * 64;
    const int tid = threadIdx.x;
    const int tx = tid & 15;
    const int ty = tid >> 4;

    const int nk = K >> 5;
    float4 va, vb0, vb1;

#define LOAD_A(kk)                                                           \
    do {                                                                     \
        if (TRANSA) {                                                        \
            int k = tid >> 3;                                                \
            int r4 = (tid & 7) << 2;                                         \
            va = *(const float4*)(A + (size_t)((kk) + k) * R + r0 + r4);     \
        } else {                                                             \
            int r = tid >> 3;                                                \
            int k4 = (tid & 7) << 2;                                         \
            va = *(const float4*)(A + (size_t)(r0 + r) * K + (kk) + k4);     \
        }                                                                    \
    } while (0)

#define LOAD_B(kk)                                                               \
    do {                                                                         \
        if (TRANSB) {                                                            \
            int o = tid >> 2;                                                    \
            int k4 = (tid & 3) << 3;                                             \
            vb0 = *(const float4*)(Bm + (size_t)(o0 + o) * K + (kk) + k4);       \
            vb1 = *(const float4*)(Bm + (size_t)(o0 + o) * K + (kk) + k4 + 4);   \
        } else {                                                                 \
            int k = tid >> 3;                                                    \
            int o8 = (tid & 7) << 3;                                             \
            vb0 = *(const float4*)(Bm + (size_t)((kk) + k) * O + o0 + o8);       \
            vb1 = *(const float4*)(Bm + (size_t)((kk) + k) * O + o0 + o8 + 4);   \
        }                                                                        \
    } while (0)

#define STORE_STAGE(buf)                                                     \
    do {                                                                     \
        if (TRANSA) {                                                        \
            int k = tid >> 3;                                                \
            int r4 = (tid & 7) << 2;                                         \
            As[buf][k][r4 + 0] = va.x; As[buf][k][r4 + 1] = va.y;            \
            As[buf][k][r4 + 2] = va.z; As[buf][k][r4 + 3] = va.w;            \
        } else {                                                             \
            int r = tid >> 3;                                                \
            int k4 = (tid & 7) << 2;                                         \
            As[buf][k4 + 0][r] = va.x; As[buf][k4 + 1][r] = va.y;            \
            As[buf][k4 + 2][r] = va.z; As[buf][k4 + 3][r] = va.w;            \
        }                                                                    \
        if (TRANSB) {                                                        \
            int o = tid >> 2;                                                \
            int k4 = (tid & 3) << 3;                                         \
            Bs[buf][k4 + 0][o] = vb0.x; Bs[buf][k4 + 1][o] = vb0.y;          \
            Bs[buf][k4 + 2][o] = vb0.z; Bs[buf][k4 + 3][o] = vb0.w;          \
            Bs[buf][k4 + 4][o] = vb1.x; Bs[buf][k4 + 5][o] = vb1.y;          \
            Bs[buf][k4 + 6][o] = vb1.z; Bs[buf][k4 + 7][o] = vb1.w;          \
        } else {                                                             \
            int k = tid >> 3;                                                \
            int o8 = (tid & 7) << 3;                                         \
            *(float4*)&Bs[buf][k][o8] = vb0;                                 \
            *(float4*)&Bs[buf][k][o8 + 4] = vb1;                             \
        }                                                                    \
    } while (0)

    float acc[2][4];
#pragma unroll
    for (int i = 0; i < 2; i++)
#pragma unroll
        for (int j = 0; j < 4; j++) acc[i][j] = 0.f;

    LOAD_A(0);
    LOAD_B(0);
    STORE_STAGE(0);
    __syncthreads();

    int cur = 0;
    for (int kki = 0; kki < nk; kki++) {
        if (kki + 1 < nk) {
            LOAD_A((kki + 1) << 5);
            LOAD_B((kki + 1) << 5);
        }
#pragma unroll
        for (int k = 0; k < 32; k++) {
            float a0 = As[cur][k][ty * 2 + 0];
            float a1 = As[cur][k][ty * 2 + 1];
            float4 b4 = *(const float4*)&Bs[cur][k][tx << 2];
            acc[0][0] = fmaf(a0, b4.x, acc[0][0]); acc[0][1] = fmaf(a0, b4.y, acc[0][1]);
            acc[0][2] = fmaf(a0, b4.z, acc[0][2]); acc[0][3] = fmaf(a0, b4.w, acc[0][3]);
            acc[1][0] = fmaf(a1, b4.x, acc[1][0]); acc[1][1] = fmaf(a1, b4.y, acc[1][1]);
            acc[1][2] = fmaf(a1, b4.z, acc[1][2]); acc[1][3] = fmaf(a1, b4.w, acc[1][3]);
        }
        if (kki + 1 < nk) STORE_STAGE(cur ^ 1);
        __syncthreads();
        cur ^= 1;
    }
#pragma unroll
    for (int i = 0; i < 2; i++) {
        int r = r0 + ty * 2 + i;
        float4 v;
        v.x = acc[i][0]; v.y = acc[i][1]; v.z = acc[i][2]; v.w = acc[i][3];
        *(float4*)(C + (size_t)r * O + o0 + (tx << 2)) = v;
    }
#undef LOAD_A
#undef LOAD_B
#undef STORE_STAGE
}

// ---------------- fused slot LN + qb + qk GEMM (iter 0 only) ----------------
__global__ void __launch_bounds__(256)
lnqk_kernel(const float* __restrict__ gpar, const float* __restrict__ bpar) {
    const int b = blockIdx.x;
    const int t = threadIdx.x;
    const int w = t >> 5, l = t & 31;
    __shared__ float sn[NS][Db];
    __shared__ float qbs[NS];

    const float4* sr = (const float4*)&g_slots[(b * NS + w) * Db];
    float4 a = sr[l * 2], c = sr[l * 2 + 1];
    float x[8] = {a.x, a.y, a.z, a.w, c.x, c.y, c.z, c.w};
    float s = 0.f, s2 = 0.f;
#pragma unroll
    for (int k = 0; k < 8; k++) {
        s += x[k];
        s2 = fmaf(x[k], x[k], s2);
    }
#pragma unroll
    for (int o = 16; o; o >>= 1) {
        s += __shfl_xor_sync(0xffffffffu, s, o);
        s2 += __shfl_xor_sync(0xffffffffu, s2, o);
    }
    float mean = s * (1.f / Db);
    float rstd = rsqrtf(s2 * (1.f / Db) - mean * mean + EPS_LN);
    float4 ga = ((const float4*)gpar)[l * 2], gc = ((const float4*)gpar)[l * 2 + 1];
    float4 ba = ((const float4*)bpar)[l * 2], bc = ((const float4*)bpar)[l * 2 + 1];
    float gg[8] = {ga.x, ga.y, ga.z, ga.w, gc.x, gc.y, gc.z, gc.w};
    float bb[8] = {ba.x, ba.y, ba.z, ba.w, bc.x, bc.y, bc.z, bc.w};
    float4 wa = ((const float4*)g_wqbk)[l * 2], wc = ((const float4*)g_wqbk)[l * 2 + 1];
    float wq[8] = {wa.x, wa.y, wa.z, wa.w, wc.x, wc.y, wc.z, wc.w};
    float p = 0.f;
#pragma unroll
    for (int k = 0; k < 8; k++) {
        float v = (x[k] - mean) * rstd * gg[k] + bb[k];
        sn[w][l * 8 + k] = v;
        p = fmaf(v, wq[k], p);
    }
#pragma unroll
    for (int o = 16; o; o >>= 1) p += __shfl_xor_sync(0xffffffffu, p, o);
    if (l == 0) qbs[w] = p + g_bqbk[0];
    __syncthreads();
    if (t < NS) g_qb[b * NS + t] = qbs[t];

    float acc[NS];
#pragma unroll
    for (int i = 0; i < NS; i++) acc[i] = g_bqk[t];
    for (int k = 0; k < Db; k += 4) {
        float w0 = g_Wqk[(k + 0) * Db + t];
        float w1 = g_Wqk[(k + 1) * Db + t];
        float w2 = g_Wqk[(k + 2) * Db + t];
        float w3 = g_Wqk[(k + 3) * Db + t];
#pragma unroll
        for (int i = 0; i < NS; i++) {
            float4 s4 = *(const float4*)&sn[i][k];
            acc[i] = fmaf(s4.x, w0, acc[i]);
            acc[i] = fmaf(s4.y, w1, acc[i]);
            acc[i] = fmaf(s4.z, w2, acc[i]);
            acc[i] = fmaf(s4.w, w3, acc[i]);
        }
    }
#pragma unroll
    for (int i = 0; i < NS; i++) g_qk[(b * NS + i) * Db + t] = acc[i];
}

// ---------------- main fused pass (R7, measured 77us): cp.async staging ring ----------------
__global__ void __launch_bounds__(256, 1)
main_pass_kernel(const float* __restrict__ inputs, const float* __restrict__ ln_g,
                 const float* __restrict__ ln_b, int reverse) {
    __shared__ float stage[8][4][Db];
    __shared__ float sU[NS * Db];
    __shared__ float sZ[NS];

    const int batch = blockIdx.x / NBLK;
    const int chunk = blockIdx.x % NBLK;
    const int tid = threadIdx.x;
    const int w = tid >> 5, l = tid & 31;

    float2 g2[4], b2[4];
    {
        float4 a = ((const float4*)ln_g)[l * 2];
        float4 c = ((const float4*)ln_g)[l * 2 + 1];
        float4 d = ((const float4*)ln_b)[l * 2];
        float4 e = ((const float4*)ln_b)[l * 2 + 1];
        g2[0] = make_float2(a.x, a.y); g2[1] = make_float2(a.z, a.w);
        g2[2] = make_float2(c.x, c.y); g2[3] = make_float2(c.z, c.w);
        b2[0] = make_float2(d.x, d.y); b2[1] = make_float2(d.z, d.w);
        b2[2] = make_float2(e.x, e.y); b2[3] = make_float2(e.z, e.w);
    }

    float2 qkg2[NS][4];
    float A_[NS], Bc[NS];
    {
        const float4* qkb = (const float4*)&g_qk[batch * NS * Db];
#pragma unroll
        for (int i = 0; i < NS; i++) {
            float4 a = qkb[i * 64 + l * 2];
            float4 c = qkb[i * 64 + l * 2 + 1];
            float2 q2[4] = {make_float2(a.x, a.y), make_float2(a.z, a.w),
                            make_float2(c.x, c.y), make_float2(c.z, c.w)};
            float2 aL = make_float2(0.f, 0.f), bL = make_float2(0.f, 0.f);
#pragma unroll
            for (int k = 0; k < 4; k++) {
                aL = f2fma(q2[k], g2[k], aL);
                bL = f2fma(q2[k], b2[k], bL);
                qkg2[i][k] = f2mul(f2mul(q2[k], g2[k]),
                                   make_float2(ATT_SCALE, ATT_SCALE));
            }
            A_[i] = aL.x + aL.y;
            Bc[i] = bL.x + bL.y;
        }
#pragma unroll
        for (int o = 16; o; o >>= 1) {
#pragma unroll
            for (int i = 0; i < NS; i++) {
                A_[i] += __shfl_xor_sync(0xffffffffu, A_[i], o);
                Bc[i] += __shfl_xor_sync(0xffffffffu, Bc[i], o);
            }
        }
#pragma unroll
        for (int i = 0; i < NS; i++) {
            A_[i] *= ATT_SCALE;
            Bc[i] = (Bc[i] + g_qb[batch * NS + i]) * ATT_SCALE;
        }
    }

    float2 U2[NS][4];
    float Z[NS];
#pragma unroll
    for (int i = 0; i < NS; i++) {
        Z[i] = 0.f;
#pragma unroll
        for (int k = 0; k < 4; k++) U2[i][k] = make_float2(0.f, 0.f);
    }

    const int TPW = NTOK / NBLK / 8;  // 128
    const int base = chunk * (NTOK / NBLK) + w * TPW;
    const float* src_base = inputs + (size_t)batch * NTOK * Db + l * 8;
    uint32_t st_base;
    {
        void* p = &stage[w][0][l * 8];
        st_base = (uint32_t)__cvta_generic_to_shared(p);
    }

#pragma unroll
    for (int j = 0; j < 3; j++) {
        int tok = reverse ? (base + TPW - 1 - j) : (base + j);
        const float* s = src_base + (size_t)tok * Db;
        uint32_t d = st_base + (uint32_t)(j * Db * 4);
        cp16(d, s);
        cp16(d + 16, s + 4);
        asm volatile("cp.async.commit_group;" ::: "memory");
    }

#pragma unroll 1
    for (int tt = 0; tt < TPW; tt += 4) {
#pragma unroll
        for (int jj = 0; jj < 4; jj++) {
            int t = tt + jj;
            asm volatile("cp.async.wait_group 2;" ::: "memory");
            float4 xa = *(const float4*)&stage[w][jj][l * 8];
            float4 xc = *(const float4*)&stage[w][jj][l * 8 + 4];
            int ft = t + 3;
            if (ft < TPW) {
                int tok = reverse ? (base + TPW - 1 - ft) : (base + ft);
                const float* s = src_base + (size_t)tok * Db;
                uint32_t d = st_base + (uint32_t)((((jj + 3) & 3) * Db) * 4);
                cp16(d, s);
                cp16(d + 16, s + 4);
            }
            asm volatile("cp.async.commit_group;" ::: "memory");

            float2 x2[4];
            x2[0] = make_float2(xa.x, xa.y); x2[1] = make_float2(xa.z, xa.w);
            x2[2] = make_float2(xc.x, xc.y); x2[3] = make_float2(xc.z, xc.w);

            float2 sv = make_float2(0.f, 0.f);
            float2 qv = make_float2(0.f, 0.f);
            float2 pd2[NS];
#pragma unroll
            for (int i = 0; i < NS; i++) pd2[i] = make_float2(0.f, 0.f);
#pragma unroll
            for (int k = 0; k < 4; k++) {
                sv = f2add(sv, x2[k]);
                qv = f2fma(x2[k], x2[k], qv);
#pragma unroll
                for (int i = 0; i < NS; i++) pd2[i] = f2fma(qkg2[i][k], x2[k], pd2[i]);
            }
            float s = sv.x + sv.y;
            float s2 = qv.x + qv.y;
            float d[NS];
#pragma unroll
            for (int i = 0; i < NS; i++) d[i] = pd2[i].x + pd2[i].y;
#pragma unroll
            for (int o = 16; o; o >>= 1) {
                s += __shfl_xor_sync(0xffffffffu, s, o);
                s2 += __shfl_xor_sync(0xffffffffu, s2, o);
#pragma unroll
                for (int i = 0; i < NS; i++) d[i] += __shfl_xor_sync(0xffffffffu, d[i], o);
            }
            float mean = s * (1.f / Db);
            float rstd = rsqrtf(s2 * (1.f / Db) - mean * mean + EPS_LN);
            float mr = -mean * rstd;
            float mx = -1e30f;
#pragma unroll
            for (int i = 0; i < NS; i++) {
                d[i] = fmaf(rstd, d[i], fmaf(mr, A_[i], Bc[i]));
                mx = fmaxf(mx, d[i]);
            }
            float p[NS], se = 0.f;
#pragma unroll
            for (int i = 0; i < NS; i++) {
                p[i] = __expf(d[i] - mx);
                se += p[i];
            }
            float inv = __fdividef(1.f, se);
            float2 rstd2 = make_float2(rstd, rstd);
            float2 nm2 = make_float2(mr, mr);
            float2 xn2[4];
#pragma unroll
            for (int k = 0; k < 4; k++) {
                float2 w2 = f2mul(g2[k], rstd2);
                float2 c2 = f2fma(nm2, g2[k], b2[k]);
                xn2[k] = f2fma(x2[k], w2, c2);
            }
#pragma unroll
            for (int i = 0; i < NS; i++) {
                float pi = fmaf(p[i], inv, EPS_ATTN);
                Z[i] += pi;
                float2 pp = make_float2(pi, pi);
#pragma unroll
                for (int k = 0; k < 4; k++) U2[i][k] = f2fma(pp, xn2[k], U2[i][k]);
            }
        }
    }

    for (int ww = 0; ww < 8; ww++) {
        if (w == ww) {
#pragma unroll
            for (int i = 0; i < NS; i++) {
#pragma unroll
                for (int k = 0; k < 4; k++) {
                    int idx = i * Db + l * 8 + 2 * k;
                    if (ww == 0) {
                        sU[idx] = U2[i][k].x;
                        sU[idx + 1] = U2[i][k].y;
                    } else {
                        sU[idx] += U2[i][k].x;
                        sU[idx + 1] += U2[i][k].y;
                    }
                }
            }
            if (l == 0) {
#pragma unroll
                for (int i = 0; i < NS; i++) {
                    if (ww == 0) sZ[i] = Z[i];
                    else sZ[i] += Z[i];
                }
            }
        }
        __syncthreads();
    }
    int outb = (batch * NBLK + chunk) * NS * Db;
    for (int idx = tid; idx < NS * Db; idx += 256) g_partU[outb + idx] = sU[idx];
    if (tid < NS) g_partZ[(batch * NBLK + chunk) * NS + tid] = sZ[tid];
}

// ---------------- megatail v2: k-major weights, coalesced ----------------
template <int LAST>
__global__ void __launch_bounds__(256)
tail_kernel(const float* __restrict__ mlp_g, const float* __restrict__ mlp_b,
            const float* __restrict__ slot_g, const float* __restrict__ slot_b,
            const float* __restrict__ bhh,
            const float* __restrict__ b1, const float* __restrict__ b2,
            float* __restrict__ outp) {
    __shared__ float su[4][Db];
    __shared__ float ssl[4][Db];
    __shared__ float shn[4][Db];
    __shared__ float shl[4][Db];
    __shared__ float sm1[4][HMLP];
    __shared__ float red[8][4][2];
    __shared__ float bcast[4][2];

    const int b = blockIdx.x >> 1;
    const int s0 = (blockIdx.x & 1) * 4;
    const int tid = threadIdx.x;
    const int w = tid >> 5, l = tid & 31;

    // A: finalize u, load prev slots
#pragma unroll
    for (int si = 0; si < 4; si++) {
        int s = s0 + si;
        float Z = 0.f, U = 0.f;
#pragma unroll
        for (int c = 0; c < NBLK; c++) {
            Z += g_partZ[(b * NBLK + c) * NS + s];
            U += g_partU[((b * NBLK + c) * NS + s) * Db + tid];
        }
        su[si][tid] = U / Z;
        ssl[si][tid] = g_slots[(b * NS + s) * Db + tid];
    }
    __syncthreads();

    // B: gi/gh dual GEMM, k-major weights (coalesced LDG.32 across tid)
    float2 acc[4][3];
#pragma unroll
    for (int si = 0; si < 4; si++)
#pragma unroll
        for (int r = 0; r < 3; r++) acc[si][r] = make_float2(0.f, 0.f);
#pragma unroll 4
    for (int k = 0; k < Db; k++) {
        float wi0 = g_wcombT[(size_t)k * 768 + tid];
        float wi1 = g_wcombT[(size_t)k * 768 + 256 + tid];
        float wi2 = g_wcombT[(size_t)k * 768 + 512 + tid];
        float wh0 = g_WhhT[(size_t)k * 768 + tid];
        float wh1 = g_WhhT[(size_t)k * 768 + 256 + tid];
        float wh2 = g_WhhT[(size_t)k * 768 + 512 + tid];
#pragma unroll
        for (int si = 0; si < 4; si++) {
            float2 us = make_float2(su[si][k], ssl[si][k]);
            acc[si][0] = f2fma(us, make_float2(wi0, wh0), acc[si][0]);
            acc[si][1] = f2fma(us, make_float2(wi1, wh1), acc[si][1]);
            acc[si][2] = f2fma(us, make_float2(wi2, wh2), acc[si][2]);
        }
    }

    // C: GRU elementwise
    float hnv[4];
    {
        float bir = g_bcomb[tid], biz = g_bcomb[256 + tid], bin = g_bcomb[512 + tid];
        float bhr = bhh[tid], bhz = bhh[256 + tid], bhn = bhh[512 + tid];
#pragma unroll
        for (int si = 0; si < 4; si++) {
            float gir = acc[si][0].x + bir, ghr = acc[si][0].y + bhr;
            float giz = acc[si][1].x + biz, ghz = acc[si][1].y + bhz;
            float gin = acc[si][2].x + bin, ghn = acc[si][2].y + bhn;
            float r = 1.f / (1.f + expf(-(gir + ghr)));
            float z = 1.f / (1.f + expf(-(giz + ghz)));
            float n = tanhf(gin + r * ghn);
            hnv[si] = (1.f - z) * n + z * ssl[si][tid];
            shn[si][tid] = hnv[si];
        }
    }

    // D: mlp LayerNorm per slot
    {
        float sa[4], sq[4];
#pragma unroll
        for (int si = 0; si < 4; si++) { sa[si] = hnv[si]; sq[si] = hnv[si] * hnv[si]; }
#pragma unroll
        for (int o = 16; o; o >>= 1) {
#pragma unroll
            for (int si = 0; si < 4; si++) {
                sa[si] += __shfl_xor_sync(0xffffffffu, sa[si], o);
                sq[si] += __shfl_xor_sync(0xffffffffu, sq[si], o);
            }
        }
        if (l == 0) {
#pragma unroll
            for (int si = 0; si < 4; si++) { red[w][si][0] = sa[si]; red[w][si][1] = sq[si]; }
        }
        __syncthreads();
        if (tid < 4) {
            float A = 0.f, Q = 0.f;
#pragma unroll
            for (int ww = 0; ww < 8; ww++) { A += red[ww][tid][0]; Q += red[ww][tid][1]; }
            float m = A * (1.f / Db);
            bcast[tid][0] = m;
            bcast[tid][1] = rsqrtf(Q * (1.f / Db) - m * m + EPS_LN);
        }
        __syncthreads();
        float gmt = mlp_g[tid], bmt = mlp_b[tid];
#pragma unroll
        for (int si = 0; si < 4; si++)
            shl[si][tid] = (hnv[si] - bcast[si][0]) * bcast[si][1] * gmt + bmt;
    }
    __syncthreads();

    // E: m1 = relu(hnl @ W1^T + b1), k-major W1T
    {
        float2 e00 = make_float2(0.f, 0.f), e01 = make_float2(0.f, 0.f);
        float2 e10 = make_float2(0.f, 0.f), e11 = make_float2(0.f, 0.f);
#pragma unroll 4
        for (int k = 0; k < Db; k++) {
            float wa = g_W1T[(size_t)k * HMLP + tid];
            float wb = g_W1T[(size_t)k * HMLP + 256 + tid];
            float h0 = shl[0][k], h1 = shl[1][k], h2 = shl[2][k], h3 = shl[3][k];
            e00 = f2fma(make_float2(h0, h1), make_float2(wa, wa), e00);
            e01 = f2fma(make_float2(h2, h3), make_float2(wa, wa), e01);
            e10 = f2fma(make_float2(h0, h1), make_float2(wb, wb), e10);
            e11 = f2fma(make_float2(h2, h3), make_float2(wb, wb), e11);
        }
        float ba = b1[tid], bb = b1[256 + tid];
        sm1[0][tid] = fmaxf(e00.x + ba, 0.f);
        sm1[1][tid] = fmaxf(e00.y + ba, 0.f);
        sm1[2][tid] = fmaxf(e01.x + ba, 0.f);
        sm1[3][tid] = fmaxf(e01.y + ba, 0.f);
        sm1[0][256 + tid] = fmaxf(e10.x + bb, 0.f);
        sm1[1][256 + tid] = fmaxf(e10.y + bb, 0.f);
        sm1[2][256 + tid] = fmaxf(e11.x + bb, 0.f);
        sm1[3][256 + tid] = fmaxf(e11.y + bb, 0.f);
    }
    __syncthreads();

    // F: out = m1 @ W2^T + b2 + hn, k-major W2T
    float nv[4];
    {
        float2 o0 = make_float2(0.f, 0.f), o1 = make_float2(0.f, 0.f);
#pragma unroll 4
        for (int k = 0; k < HMLP; k++) {
            float wv = g_W2T[(size_t)k * Db + tid];
            o0 = f2fma(make_float2(sm1[0][k], sm1[1][k]), make_float2(wv, wv), o0);
            o1 = f2fma(make_float2(sm1[2][k], sm1[3][k]), make_float2(wv, wv), o1);
        }
        float bt = b2[tid];
        nv[0] = o0.x + bt + shn[0][tid];
        nv[1] = o0.y + bt + shn[1][tid];
        nv[2] = o1.x + bt + shn[2][tid];
        nv[3] = o1.y + bt + shn[3][tid];
#pragma unroll
        for (int si = 0; si < 4; si++) {
            int s = s0 + si;
            if (LAST) outp[(b * NS + s) * Db + tid] = nv[si];
            else g_slots[(b * NS + s) * Db + tid] = nv[si];
        }
    }
    if (LAST) return;

    // G: slot LayerNorm + qb for next iteration
    {
        float sa[4], sq[4];
#pragma unroll
        for (int si = 0; si < 4; si++) { sa[si] = nv[si]; sq[si] = nv[si] * nv[si]; }
#pragma unroll
        for (int o = 16; o; o >>= 1) {
#pragma unroll
            for (int si = 0; si < 4; si++) {
                sa[si] += __shfl_xor_sync(0xffffffffu, sa[si], o);
                sq[si] += __shfl_xor_sync(0xffffffffu, sq[si], o);
            }
        }
        __syncthreads();
        if (l == 0) {
#pragma unroll
            for (int si = 0; si < 4; si++) { red[w][si][0] = sa[si]; red[w][si][1] = sq[si]; }
        }
        __syncthreads();
        if (tid < 4) {
            float A = 0.f, Q = 0.f;
#pragma unroll
            for (int ww = 0; ww < 8; ww++) { A += red[ww][tid][0]; Q += red[ww][tid][1]; }
            float m = A * (1.f / Db);
            bcast[tid][0] = m;
            bcast[tid][1] = rsqrtf(Q * (1.f / Db) - m * m + EPS_LN);
        }
        __syncthreads();
        float gst = slot_g[tid], bst = slot_b[tid], wqb = g_wqbk[tid];
        float qbp[4];
#pragma unroll
        for (int si = 0; si < 4; si++) {
            float sn = (nv[si] - bcast[si][0]) * bcast[si][1] * gst + bst;
            shl[si][tid] = sn;
            qbp[si] = sn * wqb;
        }
#pragma unroll
        for (int o = 16; o; o >>= 1) {
#pragma unroll
            for (int si = 0; si < 4; si++)
                qbp[si] += __shfl_xor_sync(0xffffffffu, qbp[si], o);
        }
        if (l == 0) {
#pragma unroll
            for (int si = 0; si < 4; si++) red[w][si][0] = qbp[si];
        }
        __syncthreads();
        if (tid < 4) {
            float A = 0.f;
#pragma unroll
            for (int ww = 0; ww < 8; ww++) A += red[ww][tid][0];
            g_qb[b * NS + s0 + tid] = A + g_bqbk[0];
        }
        __syncthreads();
    }

    // H: qk = sn @ Wqk (k-major) + bqk
    {
        float2 q0 = make_float2(0.f, 0.f), q1 = make_float2(0.f, 0.f);
#pragma unroll 4
        for (int k = 0; k < Db; k++) {
            float wq = g_Wqk[(size_t)k * Db + tid];
            q0 = f2fma(make_float2(shl[0][k], shl[1][k]), make_float2(wq, wq), q0);
            q1 = f2fma(make_float2(shl[2][k], shl[3][k]), make_float2(wq, wq), q1);
        }
        float bq_ = g_bqk[tid];
        g_qk[(b * NS + s0 + 0) * Db + tid] = q0.x + bq_;
        g_qk[(b * NS + s0 + 1) * Db + tid] = q0.y + bq_;
        g_qk[(b * NS + s0 + 2) * Db + tid] = q1.x + bq_;
        g_qk[(b * NS + s0 + 3) * Db + tid] = q1.y + bq_;
    }
}

// ---------------- launch ----------------
extern "C" void kernel_launch(void* const* d_in, const int* in_sizes, int n_in,
                              void* d_out, int out_size) {
    const float* inputs = (const float*)d_in[0];
    const float* slots = (const float*)d_in[1];
    const float* ln_in_g = (const float*)d_in[3];
    const float* ln_in_b = (const float*)d_in[4];
    const float* ln_slot_g = (const float*)d_in[5];
    const float* ln_slot_b = (const float*)d_in[6];
    const float* ln_mlp_g = (const float*)d_in[7];
    const float* ln_mlp_b = (const float*)d_in[8];
    const float* Wq = (const float*)d_in[9];
    const float* bq = (const float*)d_in[10];
    const float* Wk = (const float*)d_in[11];
    const float* bk = (const float*)d_in[12];
    const float* Wv = (const float*)d_in[13];
    const float* bv = (const float*)d_in[14];
    const float* W_ih = (const float*)d_in[15];
    const float* b_ih = (const float*)d_in[16];
    const float* W_hh = (const float*)d_in[17];
    const float* b_hh = (const float*)d_in[18];
    const float* W1 = (const float*)d_in[19];
    const float* b1 = (const float*)d_in[20];
    const float* W2 = (const float*)d_in[21];
    const float* b2 = (const float*)d_in[22];
    float* out = (float*)d_out;

    float *p_Wqk, *p_wcombT, *p_WhhT, *p_W1T, *p_W2T;
    cudaGetSymbolAddress((void**)&p_Wqk, g_Wqk);
    cudaGetSymbolAddress((void**)&p_wcombT, g_wcombT);
    cudaGetSymbolAddress((void**)&p_WhhT, g_WhhT);
    cudaGetSymbolAddress((void**)&p_W1T, g_W1T);
    cudaGetSymbolAddress((void**)&p_W2T, g_W2T);

    // prep
    prep_all_kernel<<<5 + ROWS * Db / 256, 256>>>(slots, W_ih, b_ih, bv, Wq, bq, bk, Wk);
    // Wqk[k][o] = (Wq^T @ Wk)[k][o]
    gemmp_kernel<1, 0><<<dim3(8, 4), 256>>>(Wq, Wk, p_Wqk, 256, 256, 256);
    // wcombT[k][o] = (Wv^T @ W_ih^T)[k][o]
    gemmp_kernel<1, 1><<<dim3(8, 12), 256>>>(Wv, W_ih, p_wcombT, 256, 768, 256);
    // transposes: WhhT[256x768], W1T[256x512], W2T[512x256]
    transpose_kernel<<<dim3(8, 24), 256>>>(W_hh, p_WhhT, 768, 256);
    transpose_kernel<<<dim3(8, 16), 256>>>(W1, p_W1T, 512, 256);
    transpose_kernel<<<dim3(16, 8), 256>>>(W2, p_W2T, 256, 512);
    lnqk_kernel<<<NB, 256>>>(ln_slot_g, ln_slot_b);

    for (int it = 0; it < 3; it++) {
        main_pass_kernel<<<NB * NBLK, 256>>>(inputs, ln_in_g, ln_in_b, it & 1);
        if (it < 2)
            tail_kernel<0><<<NB * 2, 256>>>(ln_mlp_g, ln_mlp_b, ln_slot_g, ln_slot_b,
                                            b_hh, b1, b2, nullptr);
        else
            tail_kernel<1><<<NB * 2, 256>>>(ln_mlp_g, ln_mlp_b, ln_slot_g, ln_slot_b,
                                            b_hh, b1, b2, out);
    }
}

// round 13
// speedup vs baseline: 1.6229x; 1.6229x over previous
#include <cuda_runtime.h>
#include <stdint.h>
#include <math.h>

#define Db 256
#define NB 32
#define NTOK 4096
#define NS 8
#define HMLP 512
#define NBLK 4
#define ROWS (NB * NS)
#define EPS_LN 1e-3f
#define EPS_ATTN 1e-8f
#define ATT_SCALE 0.0625f

// ---------------- static scratch ----------------
__device__ float g_slots[ROWS * Db];
__device__ float g_qk[ROWS * Db];
__device__ float g_qb[ROWS];
__device__ float g_partU[NB * NBLK * NS * Db];
__device__ float g_partZ[NB * NBLK * NS];
__device__ float g_gi[ROWS * 3 * Db];
__device__ float g_gh[ROWS * 3 * Db];
__device__ float g_hn[ROWS * Db];
__device__ float g_m1[ROWS * HMLP];
__device__ float g_Wqk[Db * Db];
__device__ float g_wcomb[3 * Db * Db];
__device__ float g_bcomb[3 * Db];
__device__ float g_wqbk[Db];
__device__ float g_bqk[Db];
__device__ float g_bqbk[1];

// ---------------- f32x2 packed helpers (sm_103a) ----------------
union F2U { float2 f; unsigned long long u; };
__device__ __forceinline__ float2 f2fma(float2 a, float2 b, float2 c) {
    F2U A, B, C, D;
    A.f = a; B.f = b; C.f = c;
    asm("fma.rn.f32x2 %0, %1, %2, %3;" : "=l"(D.u) : "l"(A.u), "l"(B.u), "l"(C.u));
    return D.f;
}
__device__ __forceinline__ float2 f2mul(float2 a, float2 b) {
    F2U A, B, D;
    A.f = a; B.f = b;
    asm("mul.rn.f32x2 %0, %1, %2;" : "=l"(D.u) : "l"(A.u), "l"(B.u));
    return D.f;
}
__device__ __forceinline__ float2 f2add(float2 a, float2 b) {
    F2U A, B, D;
    A.f = a; B.f = b;
    asm("add.rn.f32x2 %0, %1, %2;" : "=l"(D.u) : "l"(A.u), "l"(B.u));
    return D.f;
}

__device__ __forceinline__ void cp16(uint32_t dst, const void* src) {
    asm volatile("cp.async.ca.shared.global [%0], [%1], 16;" :: "r"(dst), "l"(src) : "memory");
}

// ---------------- prep (all micro-prep + slot copy in one launch) ----------------
__global__ void prep_all_kernel(const float* __restrict__ slots,
                                const float* __restrict__ W_ih, const float* __restrict__ b_ih,
                                const float* __restrict__ bv, const float* __restrict__ Wq,
                                const float* __restrict__ bq, const float* __restrict__ bk,
                                const float* __restrict__ Wk) {
    int blk = blockIdx.x, t = threadIdx.x;
    if (blk >= 5) {
        int i = (blk - 5) * 256 + t;
        g_slots[i] = slots[i];
        return;
    }
    if (blk < 3) {
        int o = blk * Db + t;
        float acc = b_ih[o];
        for (int d = 0; d < Db; d++) acc = fmaf(W_ih[o * Db + d], bv[d], acc);
        g_bcomb[o] = acc;
    } else if (blk == 3) {
        float acc = 0.f;
        for (int c = 0; c < Db; c++) acc = fmaf(Wq[c * Db + t], bk[c], acc);
        g_wqbk[t] = acc;
        __shared__ float red[Db];
        red[t] = bq[t] * bk[t];
        __syncthreads();
        for (int s = 128; s > 0; s >>= 1) {
            if (t < s) red[t] += red[t + s];
            __syncthreads();
        }
        if (t == 0) g_bqbk[0] = red[0];
    } else {
        float acc = 0.f;
        for (int c = 0; c < Db; c++) acc = fmaf(bq[c], Wk[c * Db + t], acc);
        g_bqk[t] = acc;
    }
}

// ---------------- ping-pong GEMM (R5-proven): 32x64 tile, K-step 32 ----------------
// TRANSA: A is [K][R]. TRANSB: B is [O][K] (C=A@B^T), else [K][O].
// ASRC=1: A row r = (sum_c partU[b,c,s,:]) / (sum_c partZ[b,c,s]).
template <int TRANSA, int TRANSB, int RELU, int ASRC>
__global__ void __launch_bounds__(256, 2)
gemmp_kernel(const float* __restrict__ A, const float* __restrict__ Bm,
             const float* __restrict__ bias, const float* __restrict__ res,
             float* __restrict__ C, int R, int O, int K) {
    __shared__ float As[2][32][33];
    __shared__ float Bs[2][32][68];
    __shared__ float invZ[32];
    const int r0 = blockIdx.x * 32;
    const int o0 = blockIdx.y * 64;
    const int tid = threadIdx.x;
    const int tx = tid & 15;
    const int ty = tid >> 4;

    if (ASRC) {
        if (tid < 32) {
            int gr = r0 + tid, bi = gr >> 3, si = gr & 7;
            float zz = 0.f;
#pragma unroll
            for (int c = 0; c < NBLK; c++) zz += g_partZ[(bi * NBLK + c) * NS + si];
            invZ[tid] = 1.f / zz;
        }
        __syncthreads();
    }

    const int nk = K >> 5;
    float4 va, vb0, vb1;

#define LOAD_A(kk)                                                                        \
    do {                                                                                  \
        if (ASRC) {                                                                       \
            int r = tid >> 3;                                                             \
            int k4 = (tid & 7) << 2;                                                      \
            int gr = r0 + r, bi = gr >> 3, si = gr & 7;                                   \
            float4 s = *(const float4*)&g_partU[((bi * NBLK + 0) * NS + si) * Db + (kk) + k4]; \
            _Pragma("unroll") for (int c = 1; c < NBLK; c++) {                            \
                float4 vv = *(const float4*)&g_partU[((bi * NBLK + c) * NS + si) * Db + (kk) + k4]; \
                s.x += vv.x; s.y += vv.y; s.z += vv.z; s.w += vv.w;                       \
            }                                                                             \
            float iz = invZ[r];                                                           \
            va.x = s.x * iz; va.y = s.y * iz; va.z = s.z * iz; va.w = s.w * iz;           \
        } else if (TRANSA) {                                                              \
            int k = tid >> 3;                                                             \
            int r4 = (tid & 7) << 2;                                                      \
            va = *(const float4*)(A + (size_t)((kk) + k) * R + r0 + r4);                  \
        } else {                                                                          \
            int r = tid >> 3;                                                             \
            int k4 = (tid & 7) << 2;                                                      \
            va = *(const float4*)(A + (size_t)(r0 + r) * K + (kk) + k4);                  \
        }                                                                                 \
    } while (0)

#define LOAD_B(kk)                                                                        \
    do {                                                                                  \
        if (TRANSB) {                                                                     \
            int o = tid >> 2;                                                             \
            int k4 = (tid & 3) << 3;                                                      \
            vb0 = *(const float4*)(Bm + (size_t)(o0 + o) * K + (kk) + k4);                \
            vb1 = *(const float4*)(Bm + (size_t)(o0 + o) * K + (kk) + k4 + 4);            \
        } else {                                                                          \
            int k = tid >> 3;                                                             \
            int o8 = (tid & 7) << 3;                                                      \
            vb0 = *(const float4*)(Bm + (size_t)((kk) + k) * O + o0 + o8);                \
            vb1 = *(const float4*)(Bm + (size_t)((kk) + k) * O + o0 + o8 + 4);            \
        }                                                                                 \
    } while (0)

#define STORE_STAGE(buf)                                                                  \
    do {                                                                                  \
        if (TRANSA && !ASRC) {                                                            \
            int k = tid >> 3;                                                             \
            int r4 = (tid & 7) << 2;                                                      \
            As[buf][k][r4 + 0] = va.x; As[buf][k][r4 + 1] = va.y;                         \
            As[buf][k][r4 + 2] = va.z; As[buf][k][r4 + 3] = va.w;                         \
        } else {                                                                          \
            int r = tid >> 3;                                                             \
            int k4 = (tid & 7) << 2;                                                      \
            As[buf][k4 + 0][r] = va.x; As[buf][k4 + 1][r] = va.y;                         \
            As[buf][k4 + 2][r] = va.z; As[buf][k4 + 3][r] = va.w;                         \
        }                                                                                 \
        if (TRANSB) {                                                                     \
            int o = tid >> 2;                                                             \
            int k4 = (tid & 3) << 3;                                                      \
            Bs[buf][k4 + 0][o] = vb0.x; Bs[buf][k4 + 1][o] = vb0.y;                       \
            Bs[buf][k4 + 2][o] = vb0.z; Bs[buf][k4 + 3][o] = vb0.w;                       \
            Bs[buf][k4 + 4][o] = vb1.x; Bs[buf][k4 + 5][o] = vb1.y;                       \
            Bs[buf][k4 + 6][o] = vb1.z; Bs[buf][k4 + 7][o] = vb1.w;                       \
        } else {                                                                          \
            int k = tid >> 3;                                                             \
            int o8 = (tid & 7) << 3;                                                      \
            *(float4*)&Bs[buf][k][o8] = vb0;                                              \
            *(float4*)&Bs[buf][k][o8 + 4] = vb1;                                          \
        }                                                                                 \
    } while (0)

    float acc[2][4];
#pragma unroll
    for (int i = 0; i < 2; i++)
#pragma unroll
        for (int j = 0; j < 4; j++) acc[i][j] = 0.f;

    LOAD_A(0);
    LOAD_B(0);
    STORE_STAGE(0);
    __syncthreads();

    int cur = 0;
    for (int kki = 0; kki < nk; kki++) {
        if (kki + 1 < nk) {
            LOAD_A((kki + 1) << 5);
            LOAD_B((kki + 1) << 5);
        }
#pragma unroll
        for (int k = 0; k < 32; k++) {
            float a0 = As[cur][k][ty * 2 + 0];
            float a1 = As[cur][k][ty * 2 + 1];
            float4 b4 = *(const float4*)&Bs[cur][k][tx << 2];
            acc[0][0] = fmaf(a0, b4.x, acc[0][0]); acc[0][1] = fmaf(a0, b4.y, acc[0][1]);
            acc[0][2] = fmaf(a0, b4.z, acc[0][2]); acc[0][3] = fmaf(a0, b4.w, acc[0][3]);
            acc[1][0] = fmaf(a1, b4.x, acc[1][0]); acc[1][1] = fmaf(a1, b4.y, acc[1][1]);
            acc[1][2] = fmaf(a1, b4.z, acc[1][2]); acc[1][3] = fmaf(a1, b4.w, acc[1][3]);
        }
        if (kki + 1 < nk) STORE_STAGE(cur ^ 1);
        __syncthreads();
        cur ^= 1;
    }
#pragma unroll
    for (int i = 0; i < 2; i++) {
        int r = r0 + ty * 2 + i;
        float vv[4];
#pragma unroll
        for (int j = 0; j < 4; j++) {
            int o = o0 + (tx << 2) + j;
            float t = acc[i][j];
            if (bias) t += bias[o];
            if (RELU) t = fmaxf(t, 0.f);
            if (res) t += res[(size_t)r * O + o];
            vv[j] = t;
        }
        float4 v;
        v.x = vv[0]; v.y = vv[1]; v.z = vv[2]; v.w = vv[3];
        *(float4*)(C + (size_t)r * O + o0 + (tx << 2)) = v;
    }
#undef LOAD_A
#undef LOAD_B
#undef STORE_STAGE
}

// ---------------- fused slot LN + qb + qk GEMM (one block per batch) ----------------
__global__ void __launch_bounds__(256)
lnqk_kernel(const float* __restrict__ gpar, const float* __restrict__ bpar) {
    const int b = blockIdx.x;
    const int t = threadIdx.x;
    const int w = t >> 5, l = t & 31;
    __shared__ float sn[NS][Db];
    __shared__ float qbs[NS];

    const float4* sr = (const float4*)&g_slots[(b * NS + w) * Db];
    float4 a = sr[l * 2], c = sr[l * 2 + 1];
    float x[8] = {a.x, a.y, a.z, a.w, c.x, c.y, c.z, c.w};
    float s = 0.f, s2 = 0.f;
#pragma unroll
    for (int k = 0; k < 8; k++) {
        s += x[k];
        s2 = fmaf(x[k], x[k], s2);
    }
#pragma unroll
    for (int o = 16; o; o >>= 1) {
        s += __shfl_xor_sync(0xffffffffu, s, o);
        s2 += __shfl_xor_sync(0xffffffffu, s2, o);
    }
    float mean = s * (1.f / Db);
    float rstd = rsqrtf(s2 * (1.f / Db) - mean * mean + EPS_LN);
    float4 ga = ((const float4*)gpar)[l * 2], gc = ((const float4*)gpar)[l * 2 + 1];
    float4 ba = ((const float4*)bpar)[l * 2], bc = ((const float4*)bpar)[l * 2 + 1];
    float gg[8] = {ga.x, ga.y, ga.z, ga.w, gc.x, gc.y, gc.z, gc.w};
    float bb[8] = {ba.x, ba.y, ba.z, ba.w, bc.x, bc.y, bc.z, bc.w};
    float4 wa = ((const float4*)g_wqbk)[l * 2], wc = ((const float4*)g_wqbk)[l * 2 + 1];
    float wq[8] = {wa.x, wa.y, wa.z, wa.w, wc.x, wc.y, wc.z, wc.w};
    float p = 0.f;
#pragma unroll
    for (int k = 0; k < 8; k++) {
        float v = (x[k] - mean) * rstd * gg[k] + bb[k];
        sn[w][l * 8 + k] = v;
        p = fmaf(v, wq[k], p);
    }
#pragma unroll
    for (int o = 16; o; o >>= 1) p += __shfl_xor_sync(0xffffffffu, p, o);
    if (l == 0) qbs[w] = p + g_bqbk[0];
    __syncthreads();
    if (t < NS) g_qb[b * NS + t] = qbs[t];

    float acc[NS];
#pragma unroll
    for (int i = 0; i < NS; i++) acc[i] = g_bqk[t];
    for (int k = 0; k < Db; k += 4) {
        float w0 = g_Wqk[(k + 0) * Db + t];
        float w1 = g_Wqk[(k + 1) * Db + t];
        float w2 = g_Wqk[(k + 2) * Db + t];
        float w3 = g_Wqk[(k + 3) * Db + t];
#pragma unroll
        for (int i = 0; i < NS; i++) {
            float4 s4 = *(const float4*)&sn[i][k];
            acc[i] = fmaf(s4.x, w0, acc[i]);
            acc[i] = fmaf(s4.y, w1, acc[i]);
            acc[i] = fmaf(s4.z, w2, acc[i]);
            acc[i] = fmaf(s4.w, w3, acc[i]);
        }
    }
#pragma unroll
    for (int i = 0; i < NS; i++) g_qk[(b * NS + i) * Db + t] = acc[i];
}

// ---------------- main fused pass (R7, measured 77us): cp.async staging ring ----------------
__global__ void __launch_bounds__(256, 1)
main_pass_kernel(const float* __restrict__ inputs, const float* __restrict__ ln_g,
                 const float* __restrict__ ln_b, int reverse) {
    __shared__ float stage[8][4][Db];
    __shared__ float sU[NS * Db];
    __shared__ float sZ[NS];

    const int batch = blockIdx.x / NBLK;
    const int chunk = blockIdx.x % NBLK;
    const int tid = threadIdx.x;
    const int w = tid >> 5, l = tid & 31;

    float2 g2[4], b2[4];
    {
        float4 a = ((const float4*)ln_g)[l * 2];
        float4 c = ((const float4*)ln_g)[l * 2 + 1];
        float4 d = ((const float4*)ln_b)[l * 2];
        float4 e = ((const float4*)ln_b)[l * 2 + 1];
        g2[0] = make_float2(a.x, a.y); g2[1] = make_float2(a.z, a.w);
        g2[2] = make_float2(c.x, c.y); g2[3] = make_float2(c.z, c.w);
        b2[0] = make_float2(d.x, d.y); b2[1] = make_float2(d.z, d.w);
        b2[2] = make_float2(e.x, e.y); b2[3] = make_float2(e.z, e.w);
    }

    float2 qkg2[NS][4];
    float A_[NS], Bc[NS];
    {
        const float4* qkb = (const float4*)&g_qk[batch * NS * Db];
#pragma unroll
        for (int i = 0; i < NS; i++) {
            float4 a = qkb[i * 64 + l * 2];
            float4 c = qkb[i * 64 + l * 2 + 1];
            float2 q2[4] = {make_float2(a.x, a.y), make_float2(a.z, a.w),
                            make_float2(c.x, c.y), make_float2(c.z, c.w)};
            float2 aL = make_float2(0.f, 0.f), bL = make_float2(0.f, 0.f);
#pragma unroll
            for (int k = 0; k < 4; k++) {
                aL = f2fma(q2[k], g2[k], aL);
                bL = f2fma(q2[k], b2[k], bL);
                qkg2[i][k] = f2mul(f2mul(q2[k], g2[k]),
                                   make_float2(ATT_SCALE, ATT_SCALE));
            }
            A_[i] = aL.x + aL.y;
            Bc[i] = bL.x + bL.y;
        }
#pragma unroll
        for (int o = 16; o; o >>= 1) {
#pragma unroll
            for (int i = 0; i < NS; i++) {
                A_[i] += __shfl_xor_sync(0xffffffffu, A_[i], o);
                Bc[i] += __shfl_xor_sync(0xffffffffu, Bc[i], o);
            }
        }
#pragma unroll
        for (int i = 0; i < NS; i++) {
            A_[i] *= ATT_SCALE;
            Bc[i] = (Bc[i] + g_qb[batch * NS + i]) * ATT_SCALE;
        }
    }

    float2 U2[NS][4];
    float Z[NS];
#pragma unroll
    for (int i = 0; i < NS; i++) {
        Z[i] = 0.f;
#pragma unroll
        for (int k = 0; k < 4; k++) U2[i][k] = make_float2(0.f, 0.f);
    }

    const int TPW = NTOK / NBLK / 8;  // 128
    const int base = chunk * (NTOK / NBLK) + w * TPW;
    const float* src_base = inputs + (size_t)batch * NTOK * Db + l * 8;
    uint32_t st_base;
    {
        void* p = &stage[w][0][l * 8];
        st_base = (uint32_t)__cvta_generic_to_shared(p);
    }

#pragma unroll
    for (int j = 0; j < 3; j++) {
        int tok = reverse ? (base + TPW - 1 - j) : (base + j);
        const float* s = src_base + (size_t)tok * Db;
        uint32_t d = st_base + (uint32_t)(j * Db * 4);
        cp16(d, s);
        cp16(d + 16, s + 4);
        asm volatile("cp.async.commit_group;" ::: "memory");
    }

#pragma unroll 1
    for (int tt = 0; tt < TPW; tt += 4) {
#pragma unroll
        for (int jj = 0; jj < 4; jj++) {
            int t = tt + jj;
            asm volatile("cp.async.wait_group 2;" ::: "memory");
            float4 xa = *(const float4*)&stage[w][jj][l * 8];
            float4 xc = *(const float4*)&stage[w][jj][l * 8 + 4];
            int ft = t + 3;
            if (ft < TPW) {
                int tok = reverse ? (base + TPW - 1 - ft) : (base + ft);
                const float* s = src_base + (size_t)tok * Db;
                uint32_t d = st_base + (uint32_t)((((jj + 3) & 3) * Db) * 4);
                cp16(d, s);
                cp16(d + 16, s + 4);
            }
            asm volatile("cp.async.commit_group;" ::: "memory");

            float2 x2[4];
            x2[0] = make_float2(xa.x, xa.y); x2[1] = make_float2(xa.z, xa.w);
            x2[2] = make_float2(xc.x, xc.y); x2[3] = make_float2(xc.z, xc.w);

            float2 sv = make_float2(0.f, 0.f);
            float2 qv = make_float2(0.f, 0.f);
            float2 pd2[NS];
#pragma unroll
            for (int i = 0; i < NS; i++) pd2[i] = make_float2(0.f, 0.f);
#pragma unroll
            for (int k = 0; k < 4; k++) {
                sv = f2add(sv, x2[k]);
                qv = f2fma(x2[k], x2[k], qv);
#pragma unroll
                for (int i = 0; i < NS; i++) pd2[i] = f2fma(qkg2[i][k], x2[k], pd2[i]);
            }
            float s = sv.x + sv.y;
            float s2 = qv.x + qv.y;
            float d[NS];
#pragma unroll
            for (int i = 0; i < NS; i++) d[i] = pd2[i].x + pd2[i].y;
#pragma unroll
            for (int o = 16; o; o >>= 1) {
                s += __shfl_xor_sync(0xffffffffu, s, o);
                s2 += __shfl_xor_sync(0xffffffffu, s2, o);
#pragma unroll
                for (int i = 0; i < NS; i++) d[i] += __shfl_xor_sync(0xffffffffu, d[i], o);
            }
            float mean = s * (1.f / Db);
            float rstd = rsqrtf(s2 * (1.f / Db) - mean * mean + EPS_LN);
            float mr = -mean * rstd;
            float mx = -1e30f;
#pragma unroll
            for (int i = 0; i < NS; i++) {
                d[i] = fmaf(rstd, d[i], fmaf(mr, A_[i], Bc[i]));
                mx = fmaxf(mx, d[i]);
            }
            float p[NS], se = 0.f;
#pragma unroll
            for (int i = 0; i < NS; i++) {
                p[i] = __expf(d[i] - mx);
                se += p[i];
            }
            float inv = __fdividef(1.f, se);
            float2 rstd2 = make_float2(rstd, rstd);
            float2 nm2 = make_float2(mr, mr);
            float2 xn2[4];
#pragma unroll
            for (int k = 0; k < 4; k++) {
                float2 w2 = f2mul(g2[k], rstd2);
                float2 c2 = f2fma(nm2, g2[k], b2[k]);
                xn2[k] = f2fma(x2[k], w2, c2);
            }
#pragma unroll
            for (int i = 0; i < NS; i++) {
                float pi = fmaf(p[i], inv, EPS_ATTN);
                Z[i] += pi;
                float2 pp = make_float2(pi, pi);
#pragma unroll
                for (int k = 0; k < 4; k++) U2[i][k] = f2fma(pp, xn2[k], U2[i][k]);
            }
        }
    }

    for (int ww = 0; ww < 8; ww++) {
        if (w == ww) {
#pragma unroll
            for (int i = 0; i < NS; i++) {
#pragma unroll
                for (int k = 0; k < 4; k++) {
                    int idx = i * Db + l * 8 + 2 * k;
                    if (ww == 0) {
                        sU[idx] = U2[i][k].x;
                        sU[idx + 1] = U2[i][k].y;
                    } else {
                        sU[idx] += U2[i][k].x;
                        sU[idx + 1] += U2[i][k].y;
                    }
                }
            }
            if (l == 0) {
#pragma unroll
                for (int i = 0; i < NS; i++) {
                    if (ww == 0) sZ[i] = Z[i];
                    else sZ[i] += Z[i];
                }
            }
        }
        __syncthreads();
    }
    int outb = (batch * NBLK + chunk) * NS * Db;
    for (int idx = tid; idx < NS * Db; idx += 256) g_partU[outb + idx] = sU[idx];
    if (tid < NS) g_partZ[(batch * NBLK + chunk) * NS + tid] = sZ[tid];
}

// ---------------- GRU elementwise + LN(mlp) fused ----------------
__global__ void gru_ln_kernel(const float* __restrict__ g, const float* __restrict__ bpar) {
    int row = blockIdx.x;
    int t = threadIdx.x;
    int w = t >> 5, l = t & 31;
    const float* gi = &g_gi[row * 3 * Db];
    const float* gh = &g_gh[row * 3 * Db];
    float h = g_slots[row * Db + t];
    float r = 1.f / (1.f + expf(-(gi[t] + gh[t])));
    float z = 1.f / (1.f + expf(-(gi[Db + t] + gh[Db + t])));
    float n = tanhf(gi[2 * Db + t] + r * gh[2 * Db + t]);
    float hn = (1.f - z) * n + z * h;
    g_slots[row * Db + t] = hn;
    __shared__ float sm[8], sm2[8], bc[2];
    float s = hn, s2 = hn * hn;
#pragma unroll
    for (int o = 16; o; o >>= 1) {
        s += __shfl_xor_sync(0xffffffffu, s, o);
        s2 += __shfl_xor_sync(0xffffffffu, s2, o);
    }
    if (l == 0) { sm[w] = s; sm2[w] = s2; }
    __syncthreads();
    if (t == 0) {
        float a = 0.f, a2 = 0.f;
#pragma unroll
        for (int i = 0; i < 8; i++) { a += sm[i]; a2 += sm2[i]; }
        float m = a * (1.f / Db);
        bc[0] = m;
        bc[1] = rsqrtf(a2 * (1.f / Db) - m * m + EPS_LN);
    }
    __syncthreads();
    g_hn[row * Db + t] = (hn - bc[0]) * bc[1] * g[t] + bpar[t];
}

// ---------------- launch ----------------
extern "C" void kernel_launch(void* const* d_in, const int* in_sizes, int n_in,
                              void* d_out, int out_size) {
    const float* inputs = (const float*)d_in[0];
    const float* slots = (const float*)d_in[1];
    const float* ln_in_g = (const float*)d_in[3];
    const float* ln_in_b = (const float*)d_in[4];
    const float* ln_slot_g = (const float*)d_in[5];
    const float* ln_slot_b = (const float*)d_in[6];
    const float* ln_mlp_g = (const float*)d_in[7];
    const float* ln_mlp_b = (const float*)d_in[8];
    const float* Wq = (const float*)d_in[9];
    const float* bq = (const float*)d_in[10];
    const float* Wk = (const float*)d_in[11];
    const float* bk = (const float*)d_in[12];
    const float* Wv = (const float*)d_in[13];
    const float* bv = (const float*)d_in[14];
    const float* W_ih = (const float*)d_in[15];
    const float* b_ih = (const float*)d_in[16];
    const float* W_hh = (const float*)d_in[17];
    const float* b_hh = (const float*)d_in[18];
    const float* W1 = (const float*)d_in[19];
    const float* b1 = (const float*)d_in[20];
    const float* W2 = (const float*)d_in[21];
    const float* b2 = (const float*)d_in[22];
    float* out = (float*)d_out;

    float *p_hn, *p_m1, *p_slots, *p_Wqk, *p_wcomb, *p_gi, *p_gh, *p_bcomb;
    cudaGetSymbolAddress((void**)&p_hn, g_hn);
    cudaGetSymbolAddress((void**)&p_m1, g_m1);
    cudaGetSymbolAddress((void**)&p_slots, g_slots);
    cudaGetSymbolAddress((void**)&p_Wqk, g_Wqk);
    cudaGetSymbolAddress((void**)&p_wcomb, g_wcomb);
    cudaGetSymbolAddress((void**)&p_gi, g_gi);
    cudaGetSymbolAddress((void**)&p_gh, g_gh);
    cudaGetSymbolAddress((void**)&p_bcomb, g_bcomb);

    // (1) micro-prep + slot copy
    prep_all_kernel<<<5 + ROWS * Db / 256, 256>>>(slots, W_ih, b_ih, bv, Wq, bq, bk, Wk);
    // (2) Wqk = Wq^T @ Wk
    gemmp_kernel<1, 0, 0, 0><<<dim3(8, 4), 256>>>(Wq, Wk, nullptr, nullptr, p_Wqk, 256, 256, 256);

    for (int it = 0; it < 3; it++) {
        // (3) lnqk  (4) main_pass <-- ncu-profiled slot
        lnqk_kernel<<<NB, 256>>>(ln_slot_g, ln_slot_b);
        main_pass_kernel<<<NB * NBLK, 256>>>(inputs, ln_in_g, ln_in_b, it & 1);
        if (it == 0) {
            // wcomb = W_ih @ Wv (first needed by gi below)
            gemmp_kernel<0, 0, 0, 0><<<dim3(24, 4), 256>>>(W_ih, Wv, nullptr, nullptr, p_wcomb, 768, 256, 256);
        }
        // gi = u @ wcomb^T + bcomb (u finalized from partU/partZ in A-stage)
        gemmp_kernel<0, 1, 0, 1><<<dim3(8, 12), 256>>>(nullptr, p_wcomb, p_bcomb, nullptr, p_gi, 256, 768, 256);
        // gh = slots @ W_hh^T + b_hh
        gemmp_kernel<0, 1, 0, 0><<<dim3(8, 12), 256>>>(p_slots, W_hh, b_hh, nullptr, p_gh, 256, 768, 256);
        gru_ln_kernel<<<ROWS, 256>>>(ln_mlp_g, ln_mlp_b);
        // m1 = relu(hn @ W1^T + b1)
        gemmp_kernel<0, 1, 1, 0><<<dim3(8, 8), 256>>>(p_hn, W1, b1, nullptr, p_m1, 256, 512, 256);
        // slots = m1 @ W2^T + b2 + slots
        float* Cdst = (it == 2) ? out : p_slots;
        gemmp_kernel<0, 1, 0, 0><<<dim3(8, 4), 256>>>(p_m1, W2, b2, p_slots, Cdst, 256, 256, 512);
    }
}

// round 14
// speedup vs baseline: 1.6993x; 1.0471x over previous
#include <cuda_runtime.h>
#include <stdint.h>
#include <math.h>

#define Db 256
#define NB 32
#define NTOK 4096
#define NS 8
#define HMLP 512
#define NBLK 4
#define ROWS (NB * NS)
#define EPS_LN 1e-3f
#define EPS_ATTN 1e-8f
#define ATT_SCALE 0.0625f

// ---------------- static scratch ----------------
__device__ float g_slots[ROWS * Db];
__device__ float g_qk[ROWS * Db];
__device__ float g_qb[ROWS];
__device__ float g_partU[NB * NBLK * NS * Db];
__device__ float g_partZ[NB * NBLK * NS];
__device__ float2 g_mr[NB * NTOK];  // cached (mean, rstd) of LN(inputs)
__device__ float g_gi[ROWS * 3 * Db];
__device__ float g_gh[ROWS * 3 * Db];
__device__ float g_hn[ROWS * Db];
__device__ float g_m1[ROWS * HMLP];
__device__ float g_Wqk[Db * Db];
__device__ float g_wcomb[3 * Db * Db];
__device__ float g_bcomb[3 * Db];
__device__ float g_wqbk[Db];
__device__ float g_bqk[Db];
__device__ float g_bqbk[1];

// ---------------- f32x2 packed helpers (sm_103a) ----------------
union F2U { float2 f; unsigned long long u; };
__device__ __forceinline__ float2 f2fma(float2 a, float2 b, float2 c) {
    F2U A, B, C, D;
    A.f = a; B.f = b; C.f = c;
    asm("fma.rn.f32x2 %0, %1, %2, %3;" : "=l"(D.u) : "l"(A.u), "l"(B.u), "l"(C.u));
    return D.f;
}
__device__ __forceinline__ float2 f2mul(float2 a, float2 b) {
    F2U A, B, D;
    A.f = a; B.f = b;
    asm("mul.rn.f32x2 %0, %1, %2;" : "=l"(D.u) : "l"(A.u), "l"(B.u));
    return D.f;
}
__device__ __forceinline__ float2 f2add(float2 a, float2 b) {
    F2U A, B, D;
    A.f = a; B.f = b;
    asm("add.rn.f32x2 %0, %1, %2;" : "=l"(D.u) : "l"(A.u), "l"(B.u));
    return D.f;
}

__device__ __forceinline__ void cp16(uint32_t dst, const void* src) {
    asm volatile("cp.async.ca.shared.global [%0], [%1], 16;" :: "r"(dst), "l"(src) : "memory");
}

// ---------------- prep ----------------
__global__ void prep_all_kernel(const float* __restrict__ slots,
                                const float* __restrict__ W_ih, const float* __restrict__ b_ih,
                                const float* __restrict__ bv, const float* __restrict__ Wq,
                                const float* __restrict__ bq, const float* __restrict__ bk,
                                const float* __restrict__ Wk) {
    int blk = blockIdx.x, t = threadIdx.x;
    if (blk >= 5) {
        int i = (blk - 5) * 256 + t;
        g_slots[i] = slots[i];
        return;
    }
    if (blk < 3) {
        int o = blk * Db + t;
        float acc = b_ih[o];
        for (int d = 0; d < Db; d++) acc = fmaf(W_ih[o * Db + d], bv[d], acc);
        g_bcomb[o] = acc;
    } else if (blk == 3) {
        float acc = 0.f;
        for (int c = 0; c < Db; c++) acc = fmaf(Wq[c * Db + t], bk[c], acc);
        g_wqbk[t] = acc;
        __shared__ float red[Db];
        red[t] = bq[t] * bk[t];
        __syncthreads();
        for (int s = 128; s > 0; s >>= 1) {
            if (t < s) red[t] += red[t + s];
            __syncthreads();
        }
        if (t == 0) g_bqbk[0] = red[0];
    } else {
        float acc = 0.f;
        for (int c = 0; c < Db; c++) acc = fmaf(bq[c], Wk[c * Db + t], acc);
        g_bqk[t] = acc;
    }
}

// ---------------- ping-pong GEMM: 32x64 tile, K-step 32 ----------------
template <int TRANSA, int TRANSB, int RELU, int ASRC>
__global__ void __launch_bounds__(256, 2)
gemmp_kernel(const float* __restrict__ A, const float* __restrict__ Bm,
             const float* __restrict__ bias, const float* __restrict__ res,
             float* __restrict__ C, int R, int O, int K) {
    __shared__ float As[2][32][33];
    __shared__ float Bs[2][32][68];
    __shared__ float invZ[32];
    const int r0 = blockIdx.x * 32;
    const int o0 = blockIdx.y * 64;
    const int tid = threadIdx.x;
    const int tx = tid & 15;
    const int ty = tid >> 4;

    if (ASRC) {
        if (tid < 32) {
            int gr = r0 + tid, bi = gr >> 3, si = gr & 7;
            float zz = 0.f;
#pragma unroll
            for (int c = 0; c < NBLK; c++) zz += g_partZ[(bi * NBLK + c) * NS + si];
            invZ[tid] = 1.f / zz;
        }
        __syncthreads();
    }

    const int nk = K >> 5;
    float4 va, vb0, vb1;

#define LOAD_A(kk)                                                                        \
    do {                                                                                  \
        if (ASRC) {                                                                       \
            int r = tid >> 3;                                                             \
            int k4 = (tid & 7) << 2;                                                      \
            int gr = r0 + r, bi = gr >> 3, si = gr & 7;                                   \
            float4 s = *(const float4*)&g_partU[((bi * NBLK + 0) * NS + si) * Db + (kk) + k4]; \
            _Pragma("unroll") for (int c = 1; c < NBLK; c++) {                            \
                float4 vv = *(const float4*)&g_partU[((bi * NBLK + c) * NS + si) * Db + (kk) + k4]; \
                s.x += vv.x; s.y += vv.y; s.z += vv.z; s.w += vv.w;                       \
            }                                                                             \
            float iz = invZ[r];                                                           \
            va.x = s.x * iz; va.y = s.y * iz; va.z = s.z * iz; va.w = s.w * iz;           \
        } else if (TRANSA) {                                                              \
            int k = tid >> 3;                                                             \
            int r4 = (tid & 7) << 2;                                                      \
            va = *(const float4*)(A + (size_t)((kk) + k) * R + r0 + r4);                  \
        } else {                                                                          \
            int r = tid >> 3;                                                             \
            int k4 = (tid & 7) << 2;                                                      \
            va = *(const float4*)(A + (size_t)(r0 + r) * K + (kk) + k4);                  \
        }                                                                                 \
    } while (0)

#define LOAD_B(kk)                                                                        \
    do {                                                                                  \
        if (TRANSB) {                                                                     \
            int o = tid >> 2;                                                             \
            int k4 = (tid & 3) << 3;                                                      \
            vb0 = *(const float4*)(Bm + (size_t)(o0 + o) * K + (kk) + k4);                \
            vb1 = *(const float4*)(Bm + (size_t)(o0 + o) * K + (kk) + k4 + 4);            \
        } else {                                                                          \
            int k = tid >> 3;                                                             \
            int o8 = (tid & 7) << 3;                                                      \
            vb0 = *(const float4*)(Bm + (size_t)((kk) + k) * O + o0 + o8);                \
            vb1 = *(const float4*)(Bm + (size_t)((kk) + k) * O + o0 + o8 + 4);            \
        }                                                                                 \
    } while (0)

#define STORE_STAGE(buf)                                                                  \
    do {                                                                                  \
        if (TRANSA && !ASRC) {                                                            \
            int k = tid >> 3;                                                             \
            int r4 = (tid & 7) << 2;                                                      \
            As[buf][k][r4 + 0] = va.x; As[buf][k][r4 + 1] = va.y;                         \
            As[buf][k][r4 + 2] = va.z; As[buf][k][r4 + 3] = va.w;                         \
        } else {                                                                          \
            int r = tid >> 3;                                                             \
            int k4 = (tid & 7) << 2;                                                      \
            As[buf][k4 + 0][r] = va.x; As[buf][k4 + 1][r] = va.y;                         \
            As[buf][k4 + 2][r] = va.z; As[buf][k4 + 3][r] = va.w;                         \
        }                                                                                 \
        if (TRANSB) {                                                                     \
            int o = tid >> 2;                                                             \
            int k4 = (tid & 3) << 3;                                                      \
            Bs[buf][k4 + 0][o] = vb0.x; Bs[buf][k4 + 1][o] = vb0.y;                       \
            Bs[buf][k4 + 2][o] = vb0.z; Bs[buf][k4 + 3][o] = vb0.w;                       \
            Bs[buf][k4 + 4][o] = vb1.x; Bs[buf][k4 + 5][o] = vb1.y;                       \
            Bs[buf][k4 + 6][o] = vb1.z; Bs[buf][k4 + 7][o] = vb1.w;                       \
        } else {                                                                          \
            int k = tid >> 3;                                                             \
            int o8 = (tid & 7) << 3;                                                      \
            *(float4*)&Bs[buf][k][o8] = vb0;                                              \
            *(float4*)&Bs[buf][k][o8 + 4] = vb1;                                          \
        }                                                                                 \
    } while (0)

    float acc[2][4];
#pragma unroll
    for (int i = 0; i < 2; i++)
#pragma unroll
        for (int j = 0; j < 4; j++) acc[i][j] = 0.f;

    LOAD_A(0);
    LOAD_B(0);
    STORE_STAGE(0);
    __syncthreads();

    int cur = 0;
    for (int kki = 0; kki < nk; kki++) {
        if (kki + 1 < nk) {
            LOAD_A((kki + 1) << 5);
            LOAD_B((kki + 1) << 5);
        }
#pragma unroll
        for (int k = 0; k < 32; k++) {
            float a0 = As[cur][k][ty * 2 + 0];
            float a1 = As[cur][k][ty * 2 + 1];
            float4 b4 = *(const float4*)&Bs[cur][k][tx << 2];
            acc[0][0] = fmaf(a0, b4.x, acc[0][0]); acc[0][1] = fmaf(a0, b4.y, acc[0][1]);
            acc[0][2] = fmaf(a0, b4.z, acc[0][2]); acc[0][3] = fmaf(a0, b4.w, acc[0][3]);
            acc[1][0] = fmaf(a1, b4.x, acc[1][0]); acc[1][1] = fmaf(a1, b4.y, acc[1][1]);
            acc[1][2] = fmaf(a1, b4.z, acc[1][2]); acc[1][3] = fmaf(a1, b4.w, acc[1][3]);
        }
        if (kki + 1 < nk) STORE_STAGE(cur ^ 1);
        __syncthreads();
        cur ^= 1;
    }
#pragma unroll
    for (int i = 0; i < 2; i++) {
        int r = r0 + ty * 2 + i;
        float vv[4];
#pragma unroll
        for (int j = 0; j < 4; j++) {
            int o = o0 + (tx << 2) + j;
            float t = acc[i][j];
            if (bias) t += bias[o];
            if (RELU) t = fmaxf(t, 0.f);
            if (res) t += res[(size_t)r * O + o];
            vv[j] = t;
        }
        float4 v;
        v.x = vv[0]; v.y = vv[1]; v.z = vv[2]; v.w = vv[3];
        *(float4*)(C + (size_t)r * O + o0 + (tx << 2)) = v;
    }
#undef LOAD_A
#undef LOAD_B
#undef STORE_STAGE
}

// ---------------- merged gi/gh GEMM (z=0: gi w/ u-finalize; z=1: gh) ----------------
__global__ void __launch_bounds__(256, 2)
gigh_kernel(const float* __restrict__ W_hh, const float* __restrict__ b_hh) {
    __shared__ float As[2][32][33];
    __shared__ float Bs[2][32][68];
    __shared__ float invZ[32];
    const int z = blockIdx.z;
    const int r0 = blockIdx.x * 32;
    const int o0 = blockIdx.y * 64;
    const int tid = threadIdx.x;
    const int tx = tid & 15;
    const int ty = tid >> 4;

    if (z == 0 && tid < 32) {
        int gr = r0 + tid, bi = gr >> 3, si = gr & 7;
        float zz = 0.f;
#pragma unroll
        for (int c = 0; c < NBLK; c++) zz += g_partZ[(bi * NBLK + c) * NS + si];
        invZ[tid] = 1.f / zz;
    }
    __syncthreads();

    const float* Bsrc = z ? W_hh : g_wcomb;
    const float* bias = z ? b_hh : g_bcomb;
    float* Cout = z ? g_gh : g_gi;

    float4 va, vb0, vb1;

#define GLOAD_A(kk)                                                                           \
    do {                                                                                      \
        int r = tid >> 3;                                                                     \
        int k4 = (tid & 7) << 2;                                                              \
        if (z == 0) {                                                                         \
            int gr = r0 + r, bi = gr >> 3, si = gr & 7;                                       \
            float4 s = *(const float4*)&g_partU[((bi * NBLK + 0) * NS + si) * Db + (kk) + k4]; \
            _Pragma("unroll") for (int c = 1; c < NBLK; c++) {                                \
                float4 vv = *(const float4*)&g_partU[((bi * NBLK + c) * NS + si) * Db + (kk) + k4]; \
                s.x += vv.x; s.y += vv.y; s.z += vv.z; s.w += vv.w;                           \
            }                                                                                 \
            float iz = invZ[r];                                                               \
            va.x = s.x * iz; va.y = s.y * iz; va.z = s.z * iz; va.w = s.w * iz;               \
        } else {                                                                              \
            va = *(const float4*)&g_slots[(size_t)(r0 + r) * Db + (kk) + k4];                 \
        }                                                                                     \
    } while (0)

#define GLOAD_B(kk)                                                              \
    do {                                                                         \
        int o = tid >> 2;                                                        \
        int k4 = (tid & 3) << 3;                                                 \
        vb0 = *(const float4*)(Bsrc + (size_t)(o0 + o) * Db + (kk) + k4);        \
        vb1 = *(const float4*)(Bsrc + (size_t)(o0 + o) * Db + (kk) + k4 + 4);    \
    } while (0)

#define GSTORE(buf)                                                          \
    do {                                                                     \
        int r = tid >> 3;                                                    \
        int k4 = (tid & 7) << 2;                                             \
        As[buf][k4 + 0][r] = va.x; As[buf][k4 + 1][r] = va.y;                \
        As[buf][k4 + 2][r] = va.z; As[buf][k4 + 3][r] = va.w;                \
        int o = tid >> 2;                                                    \
        int kb = (tid & 3) << 3;                                             \
        Bs[buf][kb + 0][o] = vb0.x; Bs[buf][kb + 1][o] = vb0.y;              \
        Bs[buf][kb + 2][o] = vb0.z; Bs[buf][kb + 3][o] = vb0.w;              \
        Bs[buf][kb + 4][o] = vb1.x; Bs[buf][kb + 5][o] = vb1.y;              \
        Bs[buf][kb + 6][o] = vb1.z; Bs[buf][kb + 7][o] = vb1.w;              \
    } while (0)

    float acc[2][4];
#pragma unroll
    for (int i = 0; i < 2; i++)
#pragma unroll
        for (int j = 0; j < 4; j++) acc[i][j] = 0.f;

    GLOAD_A(0);
    GLOAD_B(0);
    GSTORE(0);
    __syncthreads();

    int cur = 0;
    for (int kki = 0; kki < 8; kki++) {
        if (kki + 1 < 8) {
            GLOAD_A((kki + 1) << 5);
            GLOAD_B((kki + 1) << 5);
        }
#pragma unroll
        for (int k = 0; k < 32; k++) {
            float a0 = As[cur][k][ty * 2 + 0];
            float a1 = As[cur][k][ty * 2 + 1];
            float4 b4 = *(const float4*)&Bs[cur][k][tx << 2];
            acc[0][0] = fmaf(a0, b4.x, acc[0][0]); acc[0][1] = fmaf(a0, b4.y, acc[0][1]);
            acc[0][2] = fmaf(a0, b4.z, acc[0][2]); acc[0][3] = fmaf(a0, b4.w, acc[0][3]);
            acc[1][0] = fmaf(a1, b4.x, acc[1][0]); acc[1][1] = fmaf(a1, b4.y, acc[1][1]);
            acc[1][2] = fmaf(a1, b4.z, acc[1][2]); acc[1][3] = fmaf(a1, b4.w, acc[1][3]);
        }
        if (kki + 1 < 8) GSTORE(cur ^ 1);
        __syncthreads();
        cur ^= 1;
    }
#pragma unroll
    for (int i = 0; i < 2; i++) {
        int r = r0 + ty * 2 + i;
        int ob = o0 + (tx << 2);
        float4 v;
        v.x = acc[i][0] + bias[ob + 0];
        v.y = acc[i][1] + bias[ob + 1];
        v.z = acc[i][2] + bias[ob + 2];
        v.w = acc[i][3] + bias[ob + 3];
        *(float4*)(Cout + (size_t)r * (3 * Db) + ob) = v;
    }
#undef GLOAD_A
#undef GLOAD_B
#undef GSTORE
}

// ---------------- fused slot LN + qb + qk GEMM (one block per batch) ----------------
__global__ void __launch_bounds__(256)
lnqk_kernel(const float* __restrict__ gpar, const float* __restrict__ bpar) {
    const int b = blockIdx.x;
    const int t = threadIdx.x;
    const int w = t >> 5, l = t & 31;
    __shared__ float sn[NS][Db];
    __shared__ float qbs[NS];

    const float4* sr = (const float4*)&g_slots[(b * NS + w) * Db];
    float4 a = sr[l * 2], c = sr[l * 2 + 1];
    float x[8] = {a.x, a.y, a.z, a.w, c.x, c.y, c.z, c.w};
    float s = 0.f, s2 = 0.f;
#pragma unroll
    for (int k = 0; k < 8; k++) {
        s += x[k];
        s2 = fmaf(x[k], x[k], s2);
    }
#pragma unroll
    for (int o = 16; o; o >>= 1) {
        s += __shfl_xor_sync(0xffffffffu, s, o);
        s2 += __shfl_xor_sync(0xffffffffu, s2, o);
    }
    float mean = s * (1.f / Db);
    float rstd = rsqrtf(s2 * (1.f / Db) - mean * mean + EPS_LN);
    float4 ga = ((const float4*)gpar)[l * 2], gc = ((const float4*)gpar)[l * 2 + 1];
    float4 ba = ((const float4*)bpar)[l * 2], bc = ((const float4*)bpar)[l * 2 + 1];
    float gg[8] = {ga.x, ga.y, ga.z, ga.w, gc.x, gc.y, gc.z, gc.w};
    float bb[8] = {ba.x, ba.y, ba.z, ba.w, bc.x, bc.y, bc.z, bc.w};
    float4 wa = ((const float4*)g_wqbk)[l * 2], wc = ((const float4*)g_wqbk)[l * 2 + 1];
    float wq[8] = {wa.x, wa.y, wa.z, wa.w, wc.x, wc.y, wc.z, wc.w};
    float p = 0.f;
#pragma unroll
    for (int k = 0; k < 8; k++) {
        float v = (x[k] - mean) * rstd * gg[k] + bb[k];
        sn[w][l * 8 + k] = v;
        p = fmaf(v, wq[k], p);
    }
#pragma unroll
    for (int o = 16; o; o >>= 1) p += __shfl_xor_sync(0xffffffffu, p, o);
    if (l == 0) qbs[w] = p + g_bqbk[0];
    __syncthreads();
    if (t < NS) g_qb[b * NS + t] = qbs[t];

    float acc[NS];
#pragma unroll
    for (int i = 0; i < NS; i++) acc[i] = g_bqk[t];
    for (int k = 0; k < Db; k += 4) {
        float w0 = g_Wqk[(k + 0) * Db + t];
        float w1 = g_Wqk[(k + 1) * Db + t];
        float w2 = g_Wqk[(k + 2) * Db + t];
        float w3 = g_Wqk[(k + 3) * Db + t];
#pragma unroll
        for (int i = 0; i < NS; i++) {
            float4 s4 = *(const float4*)&sn[i][k];
            acc[i] = fmaf(s4.x, w0, acc[i]);
            acc[i] = fmaf(s4.y, w1, acc[i]);
            acc[i] = fmaf(s4.z, w2, acc[i]);
            acc[i] = fmaf(s4.w, w3, acc[i]);
        }
    }
#pragma unroll
    for (int i = 0; i < NS; i++) g_qk[(b * NS + i) * Db + t] = acc[i];
}

// ---------------- main fused pass: cp.async ring; FIRST caches LN stats ----------------
template <int FIRST>
__global__ void __launch_bounds__(256, 1)
main_pass_kernel(const float* __restrict__ inputs, const float* __restrict__ ln_g,
                 const float* __restrict__ ln_b, int reverse) {
    __shared__ float stage[8][4][Db];
    __shared__ float sU[NS * Db];
    __shared__ float sZ[NS];

    const int batch = blockIdx.x / NBLK;
    const int chunk = blockIdx.x % NBLK;
    const int tid = threadIdx.x;
    const int w = tid >> 5, l = tid & 31;

    float2 g2[4], b2[4];
    {
        float4 a = ((const float4*)ln_g)[l * 2];
        float4 c = ((const float4*)ln_g)[l * 2 + 1];
        float4 d = ((const float4*)ln_b)[l * 2];
        float4 e = ((const float4*)ln_b)[l * 2 + 1];
        g2[0] = make_float2(a.x, a.y); g2[1] = make_float2(a.z, a.w);
        g2[2] = make_float2(c.x, c.y); g2[3] = make_float2(c.z, c.w);
        b2[0] = make_float2(d.x, d.y); b2[1] = make_float2(d.z, d.w);
        b2[2] = make_float2(e.x, e.y); b2[3] = make_float2(e.z, e.w);
    }

    float2 qkg2[NS][4];
    float A_[NS], Bc[NS];
    {
        const float4* qkb = (const float4*)&g_qk[batch * NS * Db];
#pragma unroll
        for (int i = 0; i < NS; i++) {
            float4 a = qkb[i * 64 + l * 2];
            float4 c = qkb[i * 64 + l * 2 + 1];
            float2 q2[4] = {make_float2(a.x, a.y), make_float2(a.z, a.w),
                            make_float2(c.x, c.y), make_float2(c.z, c.w)};
            float2 aL = make_float2(0.f, 0.f), bL = make_float2(0.f, 0.f);
#pragma unroll
            for (int k = 0; k < 4; k++) {
                aL = f2fma(q2[k], g2[k], aL);
                bL = f2fma(q2[k], b2[k], bL);
                qkg2[i][k] = f2mul(f2mul(q2[k], g2[k]),
                                   make_float2(ATT_SCALE, ATT_SCALE));
            }
            A_[i] = aL.x + aL.y;
            Bc[i] = bL.x + bL.y;
        }
#pragma unroll
        for (int o = 16; o; o >>= 1) {
#pragma unroll
            for (int i = 0; i < NS; i++) {
                A_[i] += __shfl_xor_sync(0xffffffffu, A_[i], o);
                Bc[i] += __shfl_xor_sync(0xffffffffu, Bc[i], o);
            }
        }
#pragma unroll
        for (int i = 0; i < NS; i++) {
            A_[i] *= ATT_SCALE;
            Bc[i] = (Bc[i] + g_qb[batch * NS + i]) * ATT_SCALE;
        }
    }

    float2 U2[NS][4];
    float Z[NS];
#pragma unroll
    for (int i = 0; i < NS; i++) {
        Z[i] = 0.f;
#pragma unroll
        for (int k = 0; k < 4; k++) U2[i][k] = make_float2(0.f, 0.f);
    }

    const int TPW = NTOK / NBLK / 8;  // 128
    const int base = chunk * (NTOK / NBLK) + w * TPW;
    const float* src_base = inputs + (size_t)batch * NTOK * Db + l * 8;
    uint32_t st_base;
    {
        void* p = &stage[w][0][l * 8];
        st_base = (uint32_t)__cvta_generic_to_shared(p);
    }

#pragma unroll
    for (int j = 0; j < 3; j++) {
        int tok = reverse ? (base + TPW - 1 - j) : (base + j);
        const float* s = src_base + (size_t)tok * Db;
        uint32_t d = st_base + (uint32_t)(j * Db * 4);
        cp16(d, s);
        cp16(d + 16, s + 4);
        asm volatile("cp.async.commit_group;" ::: "memory");
    }

    float2 mrc;
    if (!FIRST) {
        int tok0 = reverse ? (base + TPW - 1) : base;
        mrc = g_mr[batch * NTOK + tok0];
    }

#pragma unroll 1
    for (int tt = 0; tt < TPW; tt += 4) {
#pragma unroll
        for (int jj = 0; jj < 4; jj++) {
            int t = tt + jj;
            int tok_cur = reverse ? (base + TPW - 1 - t) : (base + t);
            asm volatile("cp.async.wait_group 2;" ::: "memory");
            float4 xa = *(const float4*)&stage[w][jj][l * 8];
            float4 xc = *(const float4*)&stage[w][jj][l * 8 + 4];
            int ft = t + 3;
            if (ft < TPW) {
                int tok = reverse ? (base + TPW - 1 - ft) : (base + ft);
                const float* s = src_base + (size_t)tok * Db;
                uint32_t d = st_base + (uint32_t)((((jj + 3) & 3) * Db) * 4);
                cp16(d, s);
                cp16(d + 16, s + 4);
            }
            asm volatile("cp.async.commit_group;" ::: "memory");

            float2 x2[4];
            x2[0] = make_float2(xa.x, xa.y); x2[1] = make_float2(xa.z, xa.w);
            x2[2] = make_float2(xc.x, xc.y); x2[3] = make_float2(xc.z, xc.w);

            float mean, rstd;
            float2 mr_next;
            if (!FIRST) {
                mean = mrc.x;
                rstd = mrc.y;
                if (t + 1 < TPW) {
                    int tokn = reverse ? (base + TPW - 2 - t) : (base + t + 1);
                    mr_next = g_mr[batch * NTOK + tokn];
                }
            }

            float2 pd2[NS];
#pragma unroll
            for (int i = 0; i < NS; i++) pd2[i] = make_float2(0.f, 0.f);
            float2 sv = make_float2(0.f, 0.f);
            float2 qv = make_float2(0.f, 0.f);
#pragma unroll
            for (int k = 0; k < 4; k++) {
                if (FIRST) {
                    sv = f2add(sv, x2[k]);
                    qv = f2fma(x2[k], x2[k], qv);
                }
#pragma unroll
                for (int i = 0; i < NS; i++) pd2[i] = f2fma(qkg2[i][k], x2[k], pd2[i]);
            }
            float d[NS];
#pragma unroll
            for (int i = 0; i < NS; i++) d[i] = pd2[i].x + pd2[i].y;
            if (FIRST) {
                float s = sv.x + sv.y;
                float s2 = qv.x + qv.y;
#pragma unroll
                for (int o = 16; o; o >>= 1) {
                    s += __shfl_xor_sync(0xffffffffu, s, o);
                    s2 += __shfl_xor_sync(0xffffffffu, s2, o);
#pragma unroll
                    for (int i = 0; i < NS; i++) d[i] += __shfl_xor_sync(0xffffffffu, d[i], o);
                }
                mean = s * (1.f / Db);
                rstd = rsqrtf(s2 * (1.f / Db) - mean * mean + EPS_LN);
                if (l == 0) g_mr[batch * NTOK + tok_cur] = make_float2(mean, rstd);
            } else {
#pragma unroll
                for (int o = 16; o; o >>= 1) {
#pragma unroll
                    for (int i = 0; i < NS; i++) d[i] += __shfl_xor_sync(0xffffffffu, d[i], o);
                }
            }
            float mr = -mean * rstd;
            float mx = -1e30f;
#pragma unroll
            for (int i = 0; i < NS; i++) {
                d[i] = fmaf(rstd, d[i], fmaf(mr, A_[i], Bc[i]));
                mx = fmaxf(mx, d[i]);
            }
            float p[NS], se = 0.f;
#pragma unroll
            for (int i = 0; i < NS; i++) {
                p[i] = __expf(d[i] - mx);
                se += p[i];
            }
            float inv = __fdividef(1.f, se);
            float2 rstd2 = make_float2(rstd, rstd);
            float2 nm2 = make_float2(mr, mr);
            float2 xn2[4];
#pragma unroll
            for (int k = 0; k < 4; k++) {
                float2 w2 = f2mul(g2[k], rstd2);
                float2 c2 = f2fma(nm2, g2[k], b2[k]);
                xn2[k] = f2fma(x2[k], w2, c2);
            }
#pragma unroll
            for (int i = 0; i < NS; i++) {
                float pi = fmaf(p[i], inv, EPS_ATTN);
                Z[i] += pi;
                float2 pp = make_float2(pi, pi);
#pragma unroll
                for (int k = 0; k < 4; k++) U2[i][k] = f2fma(pp, xn2[k], U2[i][k]);
            }
            if (!FIRST) mrc = mr_next;
        }
    }

    for (int ww = 0; ww < 8; ww++) {
        if (w == ww) {
#pragma unroll
            for (int i = 0; i < NS; i++) {
#pragma unroll
                for (int k = 0; k < 4; k++) {
                    int idx = i * Db + l * 8 + 2 * k;
                    if (ww == 0) {
                        sU[idx] = U2[i][k].x;
                        sU[idx + 1] = U2[i][k].y;
                    } else {
                        sU[idx] += U2[i][k].x;
                        sU[idx + 1] += U2[i][k].y;
                    }
                }
            }
            if (l == 0) {
#pragma unroll
                for (int i = 0; i < NS; i++) {
                    if (ww == 0) sZ[i] = Z[i];
                    else sZ[i] += Z[i];
                }
            }
        }
        __syncthreads();
    }
    int outb = (batch * NBLK + chunk) * NS * Db;
    for (int idx = tid; idx < NS * Db; idx += 256) g_partU[outb + idx] = sU[idx];
    if (tid < NS) g_partZ[(batch * NBLK + chunk) * NS + tid] = sZ[tid];
}

// ---------------- GRU elementwise + LN(mlp) fused ----------------
__global__ void gru_ln_kernel(const float* __restrict__ g, const float* __restrict__ bpar) {
    int row = blockIdx.x;
    int t = threadIdx.x;
    int w = t >> 5, l = t & 31;
    const float* gi = &g_gi[row * 3 * Db];
    const float* gh = &g_gh[row * 3 * Db];
    float h = g_slots[row * Db + t];
    float r = 1.f / (1.f + expf(-(gi[t] + gh[t])));
    float z = 1.f / (1.f + expf(-(gi[Db + t] + gh[Db + t])));
    float n = tanhf(gi[2 * Db + t] + r * gh[2 * Db + t]);
    float hn = (1.f - z) * n + z * h;
    g_slots[row * Db + t] = hn;
    __shared__ float sm[8], sm2[8], bc[2];
    float s = hn, s2 = hn * hn;
#pragma unroll
    for (int o = 16; o; o >>= 1) {
        s += __shfl_xor_sync(0xffffffffu, s, o);
        s2 += __shfl_xor_sync(0xffffffffu, s2, o);
    }
    if (l == 0) { sm[w] = s; sm2[w] = s2; }
    __syncthreads();
    if (t == 0) {
        float a = 0.f, a2 = 0.f;
#pragma unroll
        for (int i = 0; i < 8; i++) { a += sm[i]; a2 += sm2[i]; }
        float m = a * (1.f / Db);
        bc[0] = m;
        bc[1] = rsqrtf(a2 * (1.f / Db) - m * m + EPS_LN);
    }
    __syncthreads();
    g_hn[row * Db + t] = (hn - bc[0]) * bc[1] * g[t] + bpar[t];
}

// ---------------- launch ----------------
extern "C" void kernel_launch(void* const* d_in, const int* in_sizes, int n_in,
                              void* d_out, int out_size) {
    const float* inputs = (const float*)d_in[0];
    const float* slots = (const float*)d_in[1];
    const float* ln_in_g = (const float*)d_in[3];
    const float* ln_in_b = (const float*)d_in[4];
    const float* ln_slot_g = (const float*)d_in[5];
    const float* ln_slot_b = (const float*)d_in[6];
    const float* ln_mlp_g = (const float*)d_in[7];
    const float* ln_mlp_b = (const float*)d_in[8];
    const float* Wq = (const float*)d_in[9];
    const float* bq = (const float*)d_in[10];
    const float* Wk = (const float*)d_in[11];
    const float* bk = (const float*)d_in[12];
    const float* Wv = (const float*)d_in[13];
    const float* bv = (const float*)d_in[14];
    const float* W_ih = (const float*)d_in[15];
    const float* b_ih = (const float*)d_in[16];
    const float* W_hh = (const float*)d_in[17];
    const float* b_hh = (const float*)d_in[18];
    const float* W1 = (const float*)d_in[19];
    const float* b1 = (const float*)d_in[20];
    const float* W2 = (const float*)d_in[21];
    const float* b2 = (const float*)d_in[22];
    float* out = (float*)d_out;

    float *p_hn, *p_m1, *p_slots, *p_Wqk, *p_wcomb;
    cudaGetSymbolAddress((void**)&p_hn, g_hn);
    cudaGetSymbolAddress((void**)&p_m1, g_m1);
    cudaGetSymbolAddress((void**)&p_slots, g_slots);
    cudaGetSymbolAddress((void**)&p_Wqk, g_Wqk);
    cudaGetSymbolAddress((void**)&p_wcomb, g_wcomb);

    // (1) micro-prep + slot copy
    prep_all_kernel<<<5 + ROWS * Db / 256, 256>>>(slots, W_ih, b_ih, bv, Wq, bq, bk, Wk);
    // (2) Wqk = Wq^T @ Wk
    gemmp_kernel<1, 0, 0, 0><<<dim3(8, 4), 256>>>(Wq, Wk, nullptr, nullptr, p_Wqk, 256, 256, 256);

    for (int it = 0; it < 3; it++) {
        // (3) lnqk  (4) main_pass <-- ncu-profiled slot
        lnqk_kernel<<<NB, 256>>>(ln_slot_g, ln_slot_b);
        if (it == 0)
            main_pass_kernel<1><<<NB * NBLK, 256>>>(inputs, ln_in_g, ln_in_b, 0);
        else
            main_pass_kernel<0><<<NB * NBLK, 256>>>(inputs, ln_in_g, ln_in_b, it & 1);
        if (it == 0) {
            // wcomb = W_ih @ Wv (first needed by gigh below)
            gemmp_kernel<0, 0, 0, 0><<<dim3(24, 4), 256>>>(W_ih, Wv, nullptr, nullptr, p_wcomb, 768, 256, 256);
        }
        // gi + gh in one launch
        gigh_kernel<<<dim3(8, 12, 2), 256>>>(W_hh, b_hh);
        gru_ln_kernel<<<ROWS, 256>>>(ln_mlp_g, ln_mlp_b);
        // m1 = relu(hn @ W1^T + b1)
        gemmp_kernel<0, 1, 1, 0><<<dim3(8, 8), 256>>>(p_hn, W1, b1, nullptr, p_m1, 256, 512, 256);
        // slots = m1 @ W2^T + b2 + slots
        float* Cdst = (it == 2) ? out : p_slots;
        gemmp_kernel<0, 1, 0, 0><<<dim3(8, 4), 256>>>(p_m1, W2, b2, p_slots, Cdst, 256, 256, 512);
    }
}

// round 15
// speedup vs baseline: 1.7561x; 1.0334x over previous
#include <cuda_runtime.h>
#include <stdint.h>
#include <math.h>

#define Db 256
#define NB 32
#define NTOK 4096
#define NS 8
#define HMLP 512
#define NBLK 4
#define ROWS (NB * NS)
#define EPS_LN 1e-3f
#define EPS_ATTN 1e-8f
#define ATT_SCALE 0.0625f

// ---------------- static scratch ----------------
__device__ float g_slots[ROWS * Db];
__device__ float g_partU[NB * NBLK * NS * Db];
__device__ float g_partZ[NB * NBLK * NS];
__device__ float2 g_mr[NB * NTOK];  // cached (mean, rstd) of LN(inputs)
__device__ float g_gi[ROWS * 3 * Db];
__device__ float g_gh[ROWS * 3 * Db];
__device__ float g_hn[ROWS * Db];
__device__ float g_m1[ROWS * HMLP];
__device__ float g_Wqk[Db * Db];   // [k][o] k-major
__device__ float g_wcomb[3 * Db * Db];
__device__ float g_bcomb[3 * Db];
__device__ float g_wqbk[Db];
__device__ float g_bqk[Db];
__device__ float g_bqbk[1];

// ---------------- f32x2 packed helpers (sm_103a) ----------------
union F2U { float2 f; unsigned long long u; };
__device__ __forceinline__ float2 f2fma(float2 a, float2 b, float2 c) {
    F2U A, B, C, D;
    A.f = a; B.f = b; C.f = c;
    asm("fma.rn.f32x2 %0, %1, %2, %3;" : "=l"(D.u) : "l"(A.u), "l"(B.u), "l"(C.u));
    return D.f;
}
__device__ __forceinline__ float2 f2mul(float2 a, float2 b) {
    F2U A, B, D;
    A.f = a; B.f = b;
    asm("mul.rn.f32x2 %0, %1, %2;" : "=l"(D.u) : "l"(A.u), "l"(B.u));
    return D.f;
}
__device__ __forceinline__ float2 f2add(float2 a, float2 b) {
    F2U A, B, D;
    A.f = a; B.f = b;
    asm("add.rn.f32x2 %0, %1, %2;" : "=l"(D.u) : "l"(A.u), "l"(B.u));
    return D.f;
}

__device__ __forceinline__ void cp16(uint32_t dst, const void* src) {
    asm volatile("cp.async.ca.shared.global [%0], [%1], 16;" :: "r"(dst), "l"(src) : "memory");
}

// ---------------- prep ----------------
__global__ void prep_all_kernel(const float* __restrict__ slots,
                                const float* __restrict__ W_ih, const float* __restrict__ b_ih,
                                const float* __restrict__ bv, const float* __restrict__ Wq,
                                const float* __restrict__ bq, const float* __restrict__ bk,
                                const float* __restrict__ Wk) {
    int blk = blockIdx.x, t = threadIdx.x;
    if (blk >= 5) {
        int i = (blk - 5) * 256 + t;
        g_slots[i] = slots[i];
        return;
    }
    if (blk < 3) {
        int o = blk * Db + t;
        float acc = b_ih[o];
        for (int d = 0; d < Db; d++) acc = fmaf(W_ih[o * Db + d], bv[d], acc);
        g_bcomb[o] = acc;
    } else if (blk == 3) {
        float acc = 0.f;
        for (int c = 0; c < Db; c++) acc = fmaf(Wq[c * Db + t], bk[c], acc);
        g_wqbk[t] = acc;
        __shared__ float red[Db];
        red[t] = bq[t] * bk[t];
        __syncthreads();
        for (int s = 128; s > 0; s >>= 1) {
            if (t < s) red[t] += red[t + s];
            __syncthreads();
        }
        if (t == 0) g_bqbk[0] = red[0];
    } else {
        float acc = 0.f;
        for (int c = 0; c < Db; c++) acc = fmaf(bq[c], Wk[c * Db + t], acc);
        g_bqk[t] = acc;
    }
}

// ---------------- ping-pong GEMM: 32x64 tile, K-step 32 ----------------
template <int TRANSA, int TRANSB, int RELU>
__global__ void __launch_bounds__(256, 2)
gemmp_kernel(const float* __restrict__ A, const float* __restrict__ Bm,
             const float* __restrict__ bias, const float* __restrict__ res,
             float* __restrict__ C, int R, int O, int K) {
    __shared__ float As[2][32][33];
    __shared__ float Bs[2][32][68];
    const int r0 = blockIdx.x * 32;
    const int o0 = blockIdx.y * 64;
    const int tid = threadIdx.x;
    const int tx = tid & 15;
    const int ty = tid >> 4;

    const int nk = K >> 5;
    float4 va, vb0, vb1;

#define LOAD_A(kk)                                                           \
    do {                                                                     \
        if (TRANSA) {                                                        \
            int k = tid >> 3;                                                \
            int r4 = (tid & 7) << 2;                                         \
            va = *(const float4*)(A + (size_t)((kk) + k) * R + r0 + r4);     \
        } else {                                                             \
            int r = tid >> 3;                                                \
            int k4 = (tid & 7) << 2;                                         \
            va = *(const float4*)(A + (size_t)(r0 + r) * K + (kk) + k4);     \
        }                                                                    \
    } while (0)

#define LOAD_B(kk)                                                               \
    do {                                                                         \
        if (TRANSB) {                                                            \
            int o = tid >> 2;                                                    \
            int k4 = (tid & 3) << 3;                                             \
            vb0 = *(const float4*)(Bm + (size_t)(o0 + o) * K + (kk) + k4);       \
            vb1 = *(const float4*)(Bm + (size_t)(o0 + o) * K + (kk) + k4 + 4);   \
        } else {                                                                 \
            int k = tid >> 3;                                                    \
            int o8 = (tid & 7) << 3;                                             \
            vb0 = *(const float4*)(Bm + (size_t)((kk) + k) * O + o0 + o8);       \
            vb1 = *(const float4*)(Bm + (size_t)((kk) + k) * O + o0 + o8 + 4);   \
        }                                                                        \
    } while (0)

#define STORE_STAGE(buf)                                                     \
    do {                                                                     \
        if (TRANSA) {                                                        \
            int k = tid >> 3;                                                \
            int r4 = (tid & 7) << 2;                                         \
            As[buf][k][r4 + 0] = va.x; As[buf][k][r4 + 1] = va.y;            \
            As[buf][k][r4 + 2] = va.z; As[buf][k][r4 + 3] = va.w;            \
        } else {                                                             \
            int r = tid >> 3;                                                \
            int k4 = (tid & 7) << 2;                                         \
            As[buf][k4 + 0][r] = va.x; As[buf][k4 + 1][r] = va.y;            \
            As[buf][k4 + 2][r] = va.z; As[buf][k4 + 3][r] = va.w;            \
        }                                                                    \
        if (TRANSB) {                                                        \
            int o = tid >> 2;                                                \
            int k4 = (tid & 3) << 3;                                         \
            Bs[buf][k4 + 0][o] = vb0.x; Bs[buf][k4 + 1][o] = vb0.y;          \
            Bs[buf][k4 + 2][o] = vb0.z; Bs[buf][k4 + 3][o] = vb0.w;          \
            Bs[buf][k4 + 4][o] = vb1.x; Bs[buf][k4 + 5][o] = vb1.y;          \
            Bs[buf][k4 + 6][o] = vb1.z; Bs[buf][k4 + 7][o] = vb1.w;          \
        } else {                                                             \
            int k = tid >> 3;                                                \
            int o8 = (tid & 7) << 3;                                         \
            *(float4*)&Bs[buf][k][o8] = vb0;                                 \
            *(float4*)&Bs[buf][k][o8 + 4] = vb1;                             \
        }                                                                    \
    } while (0)

    float acc[2][4];
#pragma unroll
    for (int i = 0; i < 2; i++)
#pragma unroll
        for (int j = 0; j < 4; j++) acc[i][j] = 0.f;

    LOAD_A(0);
    LOAD_B(0);
    STORE_STAGE(0);
    __syncthreads();

    int cur = 0;
    for (int kki = 0; kki < nk; kki++) {
        if (kki + 1 < nk) {
            LOAD_A((kki + 1) << 5);
            LOAD_B((kki + 1) << 5);
        }
#pragma unroll
        for (int k = 0; k < 32; k++) {
            float a0 = As[cur][k][ty * 2 + 0];
            float a1 = As[cur][k][ty * 2 + 1];
            float4 b4 = *(const float4*)&Bs[cur][k][tx << 2];
            acc[0][0] = fmaf(a0, b4.x, acc[0][0]); acc[0][1] = fmaf(a0, b4.y, acc[0][1]);
            acc[0][2] = fmaf(a0, b4.z, acc[0][2]); acc[0][3] = fmaf(a0, b4.w, acc[0][3]);
            acc[1][0] = fmaf(a1, b4.x, acc[1][0]); acc[1][1] = fmaf(a1, b4.y, acc[1][1]);
            acc[1][2] = fmaf(a1, b4.z, acc[1][2]); acc[1][3] = fmaf(a1, b4.w, acc[1][3]);
        }
        if (kki + 1 < nk) STORE_STAGE(cur ^ 1);
        __syncthreads();
        cur ^= 1;
    }
#pragma unroll
    for (int i = 0; i < 2; i++) {
        int r = r0 + ty * 2 + i;
        float vv[4];
#pragma unroll
        for (int j = 0; j < 4; j++) {
            int o = o0 + (tx << 2) + j;
            float t = acc[i][j];
            if (bias) t += bias[o];
            if (RELU) t = fmaxf(t, 0.f);
            if (res) t += res[(size_t)r * O + o];
            vv[j] = t;
        }
        float4 v;
        v.x = vv[0]; v.y = vv[1]; v.z = vv[2]; v.w = vv[3];
        *(float4*)(C + (size_t)r * O + o0 + (tx << 2)) = v;
    }
#undef LOAD_A
#undef LOAD_B
#undef STORE_STAGE
}

// ---------------- merged gi/gh GEMM (z=0: gi w/ u-finalize; z=1: gh) ----------------
__global__ void __launch_bounds__(256, 2)
gigh_kernel(const float* __restrict__ W_hh, const float* __restrict__ b_hh) {
    __shared__ float As[2][32][33];
    __shared__ float Bs[2][32][68];
    __shared__ float invZ[32];
    const int z = blockIdx.z;
    const int r0 = blockIdx.x * 32;
    const int o0 = blockIdx.y * 64;
    const int tid = threadIdx.x;
    const int tx = tid & 15;
    const int ty = tid >> 4;

    if (z == 0 && tid < 32) {
        int gr = r0 + tid, bi = gr >> 3, si = gr & 7;
        float zz = 0.f;
#pragma unroll
        for (int c = 0; c < NBLK; c++) zz += g_partZ[(bi * NBLK + c) * NS + si];
        invZ[tid] = 1.f / zz;
    }
    __syncthreads();

    const float* Bsrc = z ? W_hh : g_wcomb;
    const float* bias = z ? b_hh : g_bcomb;
    float* Cout = z ? g_gh : g_gi;

    float4 va, vb0, vb1;

#define GLOAD_A(kk)                                                                           \
    do {                                                                                      \
        int r = tid >> 3;                                                                     \
        int k4 = (tid & 7) << 2;                                                              \
        if (z == 0) {                                                                         \
            int gr = r0 + r, bi = gr >> 3, si = gr & 7;                                       \
            float4 s = *(const float4*)&g_partU[((bi * NBLK + 0) * NS + si) * Db + (kk) + k4]; \
            _Pragma("unroll") for (int c = 1; c < NBLK; c++) {                                \
                float4 vv = *(const float4*)&g_partU[((bi * NBLK + c) * NS + si) * Db + (kk) + k4]; \
                s.x += vv.x; s.y += vv.y; s.z += vv.z; s.w += vv.w;                           \
            }                                                                                 \
            float iz = invZ[r];                                                               \
            va.x = s.x * iz; va.y = s.y * iz; va.z = s.z * iz; va.w = s.w * iz;               \
        } else {                                                                              \
            va = *(const float4*)&g_slots[(size_t)(r0 + r) * Db + (kk) + k4];                 \
        }                                                                                     \
    } while (0)

#define GLOAD_B(kk)                                                              \
    do {                                                                         \
        int o = tid >> 2;                                                        \
        int k4 = (tid & 3) << 3;                                                 \
        vb0 = *(const float4*)(Bsrc + (size_t)(o0 + o) * Db + (kk) + k4);        \
        vb1 = *(const float4*)(Bsrc + (size_t)(o0 + o) * Db + (kk) + k4 + 4);    \
    } while (0)

#define GSTORE(buf)                                                          \
    do {                                                                     \
        int r = tid >> 3;                                                    \
        int k4 = (tid & 7) << 2;                                             \
        As[buf][k4 + 0][r] = va.x; As[buf][k4 + 1][r] = va.y;                \
        As[buf][k4 + 2][r] = va.z; As[buf][k4 + 3][r] = va.w;                \
        int o = tid >> 2;                                                    \
        int kb = (tid & 3) << 3;                                             \
        Bs[buf][kb + 0][o] = vb0.x; Bs[buf][kb + 1][o] = vb0.y;              \
        Bs[buf][kb + 2][o] = vb0.z; Bs[buf][kb + 3][o] = vb0.w;              \
        Bs[buf][kb + 4][o] = vb1.x; Bs[buf][kb + 5][o] = vb1.y;              \
        Bs[buf][kb + 6][o] = vb1.z; Bs[buf][kb + 7][o] = vb1.w;              \
    } while (0)

    float acc[2][4];
#pragma unroll
    for (int i = 0; i < 2; i++)
#pragma unroll
        for (int j = 0; j < 4; j++) acc[i][j] = 0.f;

    GLOAD_A(0);
    GLOAD_B(0);
    GSTORE(0);
    __syncthreads();

    int cur = 0;
    for (int kki = 0; kki < 8; kki++) {
        if (kki + 1 < 8) {
            GLOAD_A((kki + 1) << 5);
            GLOAD_B((kki + 1) << 5);
        }
#pragma unroll
        for (int k = 0; k < 32; k++) {
            float a0 = As[cur][k][ty * 2 + 0];
            float a1 = As[cur][k][ty * 2 + 1];
            float4 b4 = *(const float4*)&Bs[cur][k][tx << 2];
            acc[0][0] = fmaf(a0, b4.x, acc[0][0]); acc[0][1] = fmaf(a0, b4.y, acc[0][1]);
            acc[0][2] = fmaf(a0, b4.z, acc[0][2]); acc[0][3] = fmaf(a0, b4.w, acc[0][3]);
            acc[1][0] = fmaf(a1, b4.x, acc[1][0]); acc[1][1] = fmaf(a1, b4.y, acc[1][1]);
            acc[1][2] = fmaf(a1, b4.z, acc[1][2]); acc[1][3] = fmaf(a1, b4.w, acc[1][3]);
        }
        if (kki + 1 < 8) GSTORE(cur ^ 1);
        __syncthreads();
        cur ^= 1;
    }
#pragma unroll
    for (int i = 0; i < 2; i++) {
        int r = r0 + ty * 2 + i;
        int ob = o0 + (tx << 2);
        float4 v;
        v.x = acc[i][0] + bias[ob + 0];
        v.y = acc[i][1] + bias[ob + 1];
        v.z = acc[i][2] + bias[ob + 2];
        v.w = acc[i][3] + bias[ob + 3];
        *(float4*)(Cout + (size_t)r * (3 * Db) + ob) = v;
    }
#undef GLOAD_A
#undef GLOAD_B
#undef GSTORE
}

// ---------------- main fused pass: slot-LN+qk prologue + cp.async ring ----------------
template <int FIRST>
__global__ void __launch_bounds__(256, 1)
main_pass_kernel(const float* __restrict__ inputs, const float* __restrict__ ln_g,
                 const float* __restrict__ ln_b, const float* __restrict__ slot_g,
                 const float* __restrict__ slot_b, int reverse) {
    __shared__ float stage[8][4][Db];   // prologue: [0..2047]=sn, [2048..4095]=qk
    __shared__ float sU[NS * Db];
    __shared__ float sZ[NS];
    __shared__ float qbs[NS];

    const int batch = blockIdx.x / NBLK;
    const int chunk = blockIdx.x % NBLK;
    const int tid = threadIdx.x;
    const int w = tid >> 5, l = tid & 31;

    float* snS = &stage[0][0][0];
    float* qkS = snS + NS * Db;

    // ---- prologue A: warp w LNs slot row w, computes qb_w ----
    {
        const float4* sr = (const float4*)&g_slots[(batch * NS + w) * Db];
        float4 a = sr[l * 2], c = sr[l * 2 + 1];
        float x[8] = {a.x, a.y, a.z, a.w, c.x, c.y, c.z, c.w};
        float s = 0.f, s2 = 0.f;
#pragma unroll
        for (int k = 0; k < 8; k++) {
            s += x[k];
            s2 = fmaf(x[k], x[k], s2);
        }
#pragma unroll
        for (int o = 16; o; o >>= 1) {
            s += __shfl_xor_sync(0xffffffffu, s, o);
            s2 += __shfl_xor_sync(0xffffffffu, s2, o);
        }
        float mean = s * (1.f / Db);
        float rstd = rsqrtf(s2 * (1.f / Db) - mean * mean + EPS_LN);
        float4 ga = ((const float4*)slot_g)[l * 2], gc = ((const float4*)slot_g)[l * 2 + 1];
        float4 ba = ((const float4*)slot_b)[l * 2], bc = ((const float4*)slot_b)[l * 2 + 1];
        float gg[8] = {ga.x, ga.y, ga.z, ga.w, gc.x, gc.y, gc.z, gc.w};
        float bb[8] = {ba.x, ba.y, ba.z, ba.w, bc.x, bc.y, bc.z, bc.w};
        float4 wa = ((const float4*)g_wqbk)[l * 2], wc = ((const float4*)g_wqbk)[l * 2 + 1];
        float wq[8] = {wa.x, wa.y, wa.z, wa.w, wc.x, wc.y, wc.z, wc.w};
        float p = 0.f;
#pragma unroll
        for (int k = 0; k < 8; k++) {
            float v = (x[k] - mean) * rstd * gg[k] + bb[k];
            snS[w * Db + l * 8 + k] = v;
            p = fmaf(v, wq[k], p);
        }
#pragma unroll
        for (int o = 16; o; o >>= 1) p += __shfl_xor_sync(0xffffffffu, p, o);
        if (l == 0) qbs[w] = p + g_bqbk[0];
    }
    __syncthreads();

    // ---- prologue B: qk[i][tid] = sn[i] . Wqk[:,tid] + bqk[tid] (thread = column) ----
    {
        float acc[NS];
#pragma unroll
        for (int i = 0; i < NS; i++) acc[i] = g_bqk[tid];
        for (int k = 0; k < Db; k += 4) {
            float w0 = g_Wqk[(k + 0) * Db + tid];
            float w1 = g_Wqk[(k + 1) * Db + tid];
            float w2 = g_Wqk[(k + 2) * Db + tid];
            float w3 = g_Wqk[(k + 3) * Db + tid];
#pragma unroll
            for (int i = 0; i < NS; i++) {
                float4 s4 = *(const float4*)&snS[i * Db + k];
                acc[i] = fmaf(s4.x, w0, acc[i]);
                acc[i] = fmaf(s4.y, w1, acc[i]);
                acc[i] = fmaf(s4.z, w2, acc[i]);
                acc[i] = fmaf(s4.w, w3, acc[i]);
            }
        }
#pragma unroll
        for (int i = 0; i < NS; i++) qkS[i * Db + tid] = acc[i];
    }
    __syncthreads();

    // ---- per-lane LN params and qkg2/A_/Bc (from smem qk) ----
    float2 g2[4], b2[4];
    {
        float4 a = ((const float4*)ln_g)[l * 2];
        float4 c = ((const float4*)ln_g)[l * 2 + 1];
        float4 d = ((const float4*)ln_b)[l * 2];
        float4 e = ((const float4*)ln_b)[l * 2 + 1];
        g2[0] = make_float2(a.x, a.y); g2[1] = make_float2(a.z, a.w);
        g2[2] = make_float2(c.x, c.y); g2[3] = make_float2(c.z, c.w);
        b2[0] = make_float2(d.x, d.y); b2[1] = make_float2(d.z, d.w);
        b2[2] = make_float2(e.x, e.y); b2[3] = make_float2(e.z, e.w);
    }

    float2 qkg2[NS][4];
    float A_[NS], Bc[NS];
    {
#pragma unroll
        for (int i = 0; i < NS; i++) {
            float4 a = *(const float4*)&qkS[i * Db + l * 8];
            float4 c = *(const float4*)&qkS[i * Db + l * 8 + 4];
            float2 q2[4] = {make_float2(a.x, a.y), make_float2(a.z, a.w),
                            make_float2(c.x, c.y), make_float2(c.z, c.w)};
            float2 aL = make_float2(0.f, 0.f), bL = make_float2(0.f, 0.f);
#pragma unroll
            for (int k = 0; k < 4; k++) {
                aL = f2fma(q2[k], g2[k], aL);
                bL = f2fma(q2[k], b2[k], bL);
                qkg2[i][k] = f2mul(f2mul(q2[k], g2[k]),
                                   make_float2(ATT_SCALE, ATT_SCALE));
            }
            A_[i] = aL.x + aL.y;
            Bc[i] = bL.x + bL.y;
        }
#pragma unroll
        for (int o = 16; o; o >>= 1) {
#pragma unroll
            for (int i = 0; i < NS; i++) {
                A_[i] += __shfl_xor_sync(0xffffffffu, A_[i], o);
                Bc[i] += __shfl_xor_sync(0xffffffffu, Bc[i], o);
            }
        }
#pragma unroll
        for (int i = 0; i < NS; i++) {
            A_[i] *= ATT_SCALE;
            Bc[i] = (Bc[i] + qbs[i]) * ATT_SCALE;
        }
    }
    __syncthreads();  // all reads of snS/qkS done before stage reuse

    float2 U2[NS][4];
    float Z[NS];
#pragma unroll
    for (int i = 0; i < NS; i++) {
        Z[i] = 0.f;
#pragma unroll
        for (int k = 0; k < 4; k++) U2[i][k] = make_float2(0.f, 0.f);
    }

    const int TPW = NTOK / NBLK / 8;  // 128
    const int base = chunk * (NTOK / NBLK) + w * TPW;
    const float* src_base = inputs + (size_t)batch * NTOK * Db + l * 8;
    uint32_t st_base;
    {
        void* p = &stage[w][0][l * 8];
        st_base = (uint32_t)__cvta_generic_to_shared(p);
    }

#pragma unroll
    for (int j = 0; j < 3; j++) {
        int tok = reverse ? (base + TPW - 1 - j) : (base + j);
        const float* s = src_base + (size_t)tok * Db;
        uint32_t d = st_base + (uint32_t)(j * Db * 4);
        cp16(d, s);
        cp16(d + 16, s + 4);
        asm volatile("cp.async.commit_group;" ::: "memory");
    }

    float2 mrc;
    if (!FIRST) {
        int tok0 = reverse ? (base + TPW - 1) : base;
        mrc = g_mr[batch * NTOK + tok0];
    }

#pragma unroll 1
    for (int tt = 0; tt < TPW; tt += 4) {
#pragma unroll
        for (int jj = 0; jj < 4; jj++) {
            int t = tt + jj;
            int tok_cur = reverse ? (base + TPW - 1 - t) : (base + t);
            asm volatile("cp.async.wait_group 2;" ::: "memory");
            float4 xa = *(const float4*)&stage[w][jj][l * 8];
            float4 xc = *(const float4*)&stage[w][jj][l * 8 + 4];
            int ft = t + 3;
            if (ft < TPW) {
                int tok = reverse ? (base + TPW - 1 - ft) : (base + ft);
                const float* s = src_base + (size_t)tok * Db;
                uint32_t d = st_base + (uint32_t)((((jj + 3) & 3) * Db) * 4);
                cp16(d, s);
                cp16(d + 16, s + 4);
            }
            asm volatile("cp.async.commit_group;" ::: "memory");

            float2 x2[4];
            x2[0] = make_float2(xa.x, xa.y); x2[1] = make_float2(xa.z, xa.w);
            x2[2] = make_float2(xc.x, xc.y); x2[3] = make_float2(xc.z, xc.w);

            float mean, rstd;
            float2 mr_next;
            if (!FIRST) {
                mean = mrc.x;
                rstd = mrc.y;
                if (t + 1 < TPW) {
                    int tokn = reverse ? (base + TPW - 2 - t) : (base + t + 1);
                    mr_next = g_mr[batch * NTOK + tokn];
                }
            }

            float2 pd2[NS];
#pragma unroll
            for (int i = 0; i < NS; i++) pd2[i] = make_float2(0.f, 0.f);
            float2 sv = make_float2(0.f, 0.f);
            float2 qv = make_float2(0.f, 0.f);
#pragma unroll
            for (int k = 0; k < 4; k++) {
                if (FIRST) {
                    sv = f2add(sv, x2[k]);
                    qv = f2fma(x2[k], x2[k], qv);
                }
#pragma unroll
                for (int i = 0; i < NS; i++) pd2[i] = f2fma(qkg2[i][k], x2[k], pd2[i]);
            }
            float d[NS];
#pragma unroll
            for (int i = 0; i < NS; i++) d[i] = pd2[i].x + pd2[i].y;
            if (FIRST) {
                float s = sv.x + sv.y;
                float s2 = qv.x + qv.y;
#pragma unroll
                for (int o = 16; o; o >>= 1) {
                    s += __shfl_xor_sync(0xffffffffu, s, o);
                    s2 += __shfl_xor_sync(0xffffffffu, s2, o);
#pragma unroll
                    for (int i = 0; i < NS; i++) d[i] += __shfl_xor_sync(0xffffffffu, d[i], o);
                }
                mean = s * (1.f / Db);
                rstd = rsqrtf(s2 * (1.f / Db) - mean * mean + EPS_LN);
                if (l == 0) g_mr[batch * NTOK + tok_cur] = make_float2(mean, rstd);
            } else {
#pragma unroll
                for (int o = 16; o; o >>= 1) {
#pragma unroll
                    for (int i = 0; i < NS; i++) d[i] += __shfl_xor_sync(0xffffffffu, d[i], o);
                }
            }
            float mr = -mean * rstd;
            float mx = -1e30f;
#pragma unroll
            for (int i = 0; i < NS; i++) {
                d[i] = fmaf(rstd, d[i], fmaf(mr, A_[i], Bc[i]));
                mx = fmaxf(mx, d[i]);
            }
            float p[NS], se = 0.f;
#pragma unroll
            for (int i = 0; i < NS; i++) {
                p[i] = __expf(d[i] - mx);
                se += p[i];
            }
            float inv = __fdividef(1.f, se);
            float2 rstd2 = make_float2(rstd, rstd);
            float2 nm2 = make_float2(mr, mr);
            float2 xn2[4];
#pragma unroll
            for (int k = 0; k < 4; k++) {
                float2 w2 = f2mul(g2[k], rstd2);
                float2 c2 = f2fma(nm2, g2[k], b2[k]);
                xn2[k] = f2fma(x2[k], w2, c2);
            }
#pragma unroll
            for (int i = 0; i < NS; i++) {
                float pi = fmaf(p[i], inv, EPS_ATTN);
                Z[i] += pi;
                float2 pp = make_float2(pi, pi);
#pragma unroll
                for (int k = 0; k < 4; k++) U2[i][k] = f2fma(pp, xn2[k], U2[i][k]);
            }
            if (!FIRST) mrc = mr_next;
        }
    }

    for (int ww = 0; ww < 8; ww++) {
        if (w == ww) {
#pragma unroll
            for (int i = 0; i < NS; i++) {
#pragma unroll
                for (int k = 0; k < 4; k++) {
                    int idx = i * Db + l * 8 + 2 * k;
                    if (ww == 0) {
                        sU[idx] = U2[i][k].x;
                        sU[idx + 1] = U2[i][k].y;
                    } else {
                        sU[idx] += U2[i][k].x;
                        sU[idx + 1] += U2[i][k].y;
                    }
                }
            }
            if (l == 0) {
#pragma unroll
                for (int i = 0; i < NS; i++) {
                    if (ww == 0) sZ[i] = Z[i];
                    else sZ[i] += Z[i];
                }
            }
        }
        __syncthreads();
    }
    int outb = (batch * NBLK + chunk) * NS * Db;
    for (int idx = tid; idx < NS * Db; idx += 256) g_partU[outb + idx] = sU[idx];
    if (tid < NS) g_partZ[(batch * NBLK + chunk) * NS + tid] = sZ[tid];
}

// ---------------- GRU elementwise + LN(mlp) fused ----------------
__global__ void gru_ln_kernel(const float* __restrict__ g, const float* __restrict__ bpar) {
    int row = blockIdx.x;
    int t = threadIdx.x;
    int w = t >> 5, l = t & 31;
    const float* gi = &g_gi[row * 3 * Db];
    const float* gh = &g_gh[row * 3 * Db];
    float h = g_slots[row * Db + t];
    float r = 1.f / (1.f + expf(-(gi[t] + gh[t])));
    float z = 1.f / (1.f + expf(-(gi[Db + t] + gh[Db + t])));
    float n = tanhf(gi[2 * Db + t] + r * gh[2 * Db + t]);
    float hn = (1.f - z) * n + z * h;
    g_slots[row * Db + t] = hn;
    __shared__ float sm[8], sm2[8], bc[2];
    float s = hn, s2 = hn * hn;
#pragma unroll
    for (int o = 16; o; o >>= 1) {
        s += __shfl_xor_sync(0xffffffffu, s, o);
        s2 += __shfl_xor_sync(0xffffffffu, s2, o);
    }
    if (l == 0) { sm[w] = s; sm2[w] = s2; }
    __syncthreads();
    if (t == 0) {
        float a = 0.f, a2 = 0.f;
#pragma unroll
        for (int i = 0; i < 8; i++) { a += sm[i]; a2 += sm2[i]; }
        float m = a * (1.f / Db);
        bc[0] = m;
        bc[1] = rsqrtf(a2 * (1.f / Db) - m * m + EPS_LN);
    }
    __syncthreads();
    g_hn[row * Db + t] = (hn - bc[0]) * bc[1] * g[t] + bpar[t];
}

// ---------------- launch ----------------
extern "C" void kernel_launch(void* const* d_in, const int* in_sizes, int n_in,
                              void* d_out, int out_size) {
    const float* inputs = (const float*)d_in[0];
    const float* slots = (const float*)d_in[1];
    const float* ln_in_g = (const float*)d_in[3];
    const float* ln_in_b = (const float*)d_in[4];
    const float* ln_slot_g = (const float*)d_in[5];
    const float* ln_slot_b = (const float*)d_in[6];
    const float* ln_mlp_g = (const float*)d_in[7];
    const float* ln_mlp_b = (const float*)d_in[8];
    const float* Wq = (const float*)d_in[9];
    const float* bq = (const float*)d_in[10];
    const float* Wk = (const float*)d_in[11];
    const float* bk = (const float*)d_in[12];
    const float* Wv = (const float*)d_in[13];
    const float* bv = (const float*)d_in[14];
    const float* W_ih = (const float*)d_in[15];
    const float* b_ih = (const float*)d_in[16];
    const float* W_hh = (const float*)d_in[17];
    const float* b_hh = (const float*)d_in[18];
    const float* W1 = (const float*)d_in[19];
    const float* b1 = (const float*)d_in[20];
    const float* W2 = (const float*)d_in[21];
    const float* b2 = (const float*)d_in[22];
    float* out = (float*)d_out;

    float *p_hn, *p_m1, *p_slots, *p_Wqk, *p_wcomb;
    cudaGetSymbolAddress((void**)&p_hn, g_hn);
    cudaGetSymbolAddress((void**)&p_m1, g_m1);
    cudaGetSymbolAddress((void**)&p_slots, g_slots);
    cudaGetSymbolAddress((void**)&p_Wqk, g_Wqk);
    cudaGetSymbolAddress((void**)&p_wcomb, g_wcomb);

    // (1) micro-prep + slot copy
    prep_all_kernel<<<5 + ROWS * Db / 256, 256>>>(slots, W_ih, b_ih, bv, Wq, bq, bk, Wk);
    // (2) Wqk[k][o] = (Wq^T @ Wk)
    gemmp_kernel<1, 0, 0><<<dim3(8, 4), 256>>>(Wq, Wk, nullptr, nullptr, p_Wqk, 256, 256, 256);

    for (int it = 0; it < 3; it++) {
        // (3) main_pass (with fused slot-LN + qk prologue)
        if (it == 0)
            main_pass_kernel<1><<<NB * NBLK, 256>>>(inputs, ln_in_g, ln_in_b,
                                                    ln_slot_g, ln_slot_b, 0);
        else
            main_pass_kernel<0><<<NB * NBLK, 256>>>(inputs, ln_in_g, ln_in_b,
                                                    ln_slot_g, ln_slot_b, it & 1);
        if (it == 0) {
            // wcomb = W_ih @ Wv (first needed by gigh below)
            gemmp_kernel<0, 0, 0><<<dim3(24, 4), 256>>>(W_ih, Wv, nullptr, nullptr, p_wcomb, 768, 256, 256);
        }
        // gi + gh in one launch
        gigh_kernel<<<dim3(8, 12, 2), 256>>>(W_hh, b_hh);
        gru_ln_kernel<<<ROWS, 256>>>(ln_mlp_g, ln_mlp_b);
        // m1 = relu(hn @ W1^T + b1)
        gemmp_kernel<0, 1, 1><<<dim3(8, 8), 256>>>(p_hn, W1, b1, nullptr, p_m1, 256, 512, 256);
        // slots = m1 @ W2^T + b2 + slots
        float* Cdst = (it == 2) ? out : p_slots;
        gemmp_kernel<0, 1, 0><<<dim3(8, 4), 256>>>(p_m1, W2, b2, p_slots, Cdst, 256, 256, 512);
    }
}

// round 16
// speedup vs baseline: 1.7942x; 1.0217x over previous
#include <cuda_runtime.h>
#include <stdint.h>
#include <math.h>

#define Db 256
#define NB 32
#define NTOK 4096
#define NS 8
#define HMLP 512
#define NBLK 4
#define ROWS (NB * NS)
#define EPS_LN 1e-3f
#define EPS_ATTN 1e-8f
#define ATT_SCALE 0.0625f

// ---------------- static scratch ----------------
__device__ float g_slots[ROWS * Db];
__device__ float g_partU[NB * NBLK * NS * Db];
__device__ float g_partZ[NB * NBLK * NS];
__device__ float2 g_mr[NB * NTOK];  // cached (mean, rstd) of LN(inputs)
__device__ float g_gi[ROWS * 3 * Db];
__device__ float g_gh[ROWS * 3 * Db];
__device__ float g_hn[ROWS * Db];
__device__ float g_m1[ROWS * HMLP];
__device__ float g_Wqk[Db * Db];   // [k][o] k-major
__device__ float g_wcomb[3 * Db * Db];
__device__ float g_bcomb[3 * Db];
__device__ float g_wqbk[Db];
__device__ float g_bqk[Db];
__device__ float g_bqbk[1];

// ---------------- f32x2 packed helpers (sm_103a) ----------------
union F2U { float2 f; unsigned long long u; };
__device__ __forceinline__ float2 f2fma(float2 a, float2 b, float2 c) {
    F2U A, B, C, D;
    A.f = a; B.f = b; C.f = c;
    asm("fma.rn.f32x2 %0, %1, %2, %3;" : "=l"(D.u) : "l"(A.u), "l"(B.u), "l"(C.u));
    return D.f;
}
__device__ __forceinline__ float2 f2mul(float2 a, float2 b) {
    F2U A, B, D;
    A.f = a; B.f = b;
    asm("mul.rn.f32x2 %0, %1, %2;" : "=l"(D.u) : "l"(A.u), "l"(B.u));
    return D.f;
}
__device__ __forceinline__ float2 f2add(float2 a, float2 b) {
    F2U A, B, D;
    A.f = a; B.f = b;
    asm("add.rn.f32x2 %0, %1, %2;" : "=l"(D.u) : "l"(A.u), "l"(B.u));
    return D.f;
}

__device__ __forceinline__ void cp16(uint32_t dst, const void* src) {
    asm volatile("cp.async.ca.shared.global [%0], [%1], 16;" :: "r"(dst), "l"(src) : "memory");
}

// ---------------- prep ----------------
__global__ void prep_all_kernel(const float* __restrict__ slots,
                                const float* __restrict__ W_ih, const float* __restrict__ b_ih,
                                const float* __restrict__ bv, const float* __restrict__ Wq,
                                const float* __restrict__ bq, const float* __restrict__ bk,
                                const float* __restrict__ Wk) {
    int blk = blockIdx.x, t = threadIdx.x;
    if (blk >= 5) {
        int i = (blk - 5) * 256 + t;
        g_slots[i] = slots[i];
        return;
    }
    if (blk < 3) {
        int o = blk * Db + t;
        float acc = b_ih[o];
        for (int d = 0; d < Db; d++) acc = fmaf(W_ih[o * Db + d], bv[d], acc);
        g_bcomb[o] = acc;
    } else if (blk == 3) {
        float acc = 0.f;
        for (int c = 0; c < Db; c++) acc = fmaf(Wq[c * Db + t], bk[c], acc);
        g_wqbk[t] = acc;
        __shared__ float red[Db];
        red[t] = bq[t] * bk[t];
        __syncthreads();
        for (int s = 128; s > 0; s >>= 1) {
            if (t < s) red[t] += red[t + s];
            __syncthreads();
        }
        if (t == 0) g_bqbk[0] = red[0];
    } else {
        float acc = 0.f;
        for (int c = 0; c < Db; c++) acc = fmaf(bq[c], Wk[c * Db + t], acc);
        g_bqk[t] = acc;
    }
}

// ---------------- ping-pong GEMM: 32x64 tile, K-step 32 ----------------
template <int TRANSA, int TRANSB, int RELU>
__global__ void __launch_bounds__(256, 2)
gemmp_kernel(const float* __restrict__ A, const float* __restrict__ Bm,
             const float* __restrict__ bias, const float* __restrict__ res,
             float* __restrict__ C, int R, int O, int K) {
    __shared__ float As[2][32][33];
    __shared__ float Bs[2][32][68];
    const int r0 = blockIdx.x * 32;
    const int o0 = blockIdx.y * 64;
    const int tid = threadIdx.x;
    const int tx = tid & 15;
    const int ty = tid >> 4;

    const int nk = K >> 5;
    float4 va, vb0, vb1;

#define LOAD_A(kk)                                                           \
    do {                                                                     \
        if (TRANSA) {                                                        \
            int k = tid >> 3;                                                \
            int r4 = (tid & 7) << 2;                                         \
            va = *(const float4*)(A + (size_t)((kk) + k) * R + r0 + r4);     \
        } else {                                                             \
            int r = tid >> 3;                                                \
            int k4 = (tid & 7) << 2;                                         \
            va = *(const float4*)(A + (size_t)(r0 + r) * K + (kk) + k4);     \
        }                                                                    \
    } while (0)

#define LOAD_B(kk)                                                               \
    do {                                                                         \
        if (TRANSB) {                                                            \
            int o = tid >> 2;                                                    \
            int k4 = (tid & 3) << 3;                                             \
            vb0 = *(const float4*)(Bm + (size_t)(o0 + o) * K + (kk) + k4);       \
            vb1 = *(const float4*)(Bm + (size_t)(o0 + o) * K + (kk) + k4 + 4);   \
        } else {                                                                 \
            int k = tid >> 3;                                                    \
            int o8 = (tid & 7) << 3;                                             \
            vb0 = *(const float4*)(Bm + (size_t)((kk) + k) * O + o0 + o8);       \
            vb1 = *(const float4*)(Bm + (size_t)((kk) + k) * O + o0 + o8 + 4);   \
        }                                                                        \
    } while (0)

#define STORE_STAGE(buf)                                                     \
    do {                                                                     \
        if (TRANSA) {                                                        \
            int k = tid >> 3;                                                \
            int r4 = (tid & 7) << 2;                                         \
            As[buf][k][r4 + 0] = va.x; As[buf][k][r4 + 1] = va.y;            \
            As[buf][k][r4 + 2] = va.z; As[buf][k][r4 + 3] = va.w;            \
        } else {                                                             \
            int r = tid >> 3;                                                \
            int k4 = (tid & 7) << 2;                                         \
            As[buf][k4 + 0][r] = va.x; As[buf][k4 + 1][r] = va.y;            \
            As[buf][k4 + 2][r] = va.z; As[buf][k4 + 3][r] = va.w;            \
        }                                                                    \
        if (TRANSB) {                                                        \
            int o = tid >> 2;                                                \
            int k4 = (tid & 3) << 3;                                         \
            Bs[buf][k4 + 0][o] = vb0.x; Bs[buf][k4 + 1][o] = vb0.y;          \
            Bs[buf][k4 + 2][o] = vb0.z; Bs[buf][k4 + 3][o] = vb0.w;          \
            Bs[buf][k4 + 4][o] = vb1.x; Bs[buf][k4 + 5][o] = vb1.y;          \
            Bs[buf][k4 + 6][o] = vb1.z; Bs[buf][k4 + 7][o] = vb1.w;          \
        } else {                                                             \
            int k = tid >> 3;                                                \
            int o8 = (tid & 7) << 3;                                         \
            *(float4*)&Bs[buf][k][o8] = vb0;                                 \
            *(float4*)&Bs[buf][k][o8 + 4] = vb1;                             \
        }                                                                    \
    } while (0)

    float acc[2][4];
#pragma unroll
    for (int i = 0; i < 2; i++)
#pragma unroll
        for (int j = 0; j < 4; j++) acc[i][j] = 0.f;

    LOAD_A(0);
    LOAD_B(0);
    STORE_STAGE(0);
    __syncthreads();

    int cur = 0;
    for (int kki = 0; kki < nk; kki++) {
        if (kki + 1 < nk) {
            LOAD_A((kki + 1) << 5);
            LOAD_B((kki + 1) << 5);
        }
#pragma unroll
        for (int k = 0; k < 32; k++) {
            float a0 = As[cur][k][ty * 2 + 0];
            float a1 = As[cur][k][ty * 2 + 1];
            float4 b4 = *(const float4*)&Bs[cur][k][tx << 2];
            acc[0][0] = fmaf(a0, b4.x, acc[0][0]); acc[0][1] = fmaf(a0, b4.y, acc[0][1]);
            acc[0][2] = fmaf(a0, b4.z, acc[0][2]); acc[0][3] = fmaf(a0, b4.w, acc[0][3]);
            acc[1][0] = fmaf(a1, b4.x, acc[1][0]); acc[1][1] = fmaf(a1, b4.y, acc[1][1]);
            acc[1][2] = fmaf(a1, b4.z, acc[1][2]); acc[1][3] = fmaf(a1, b4.w, acc[1][3]);
        }
        if (kki + 1 < nk) STORE_STAGE(cur ^ 1);
        __syncthreads();
        cur ^= 1;
    }
#pragma unroll
    for (int i = 0; i < 2; i++) {
        int r = r0 + ty * 2 + i;
        float vv[4];
#pragma unroll
        for (int j = 0; j < 4; j++) {
            int o = o0 + (tx << 2) + j;
            float t = acc[i][j];
            if (bias) t += bias[o];
            if (RELU) t = fmaxf(t, 0.f);
            if (res) t += res[(size_t)r * O + o];
            vv[j] = t;
        }
        float4 v;
        v.x = vv[0]; v.y = vv[1]; v.z = vv[2]; v.w = vv[3];
        *(float4*)(C + (size_t)r * O + o0 + (tx << 2)) = v;
    }
#undef LOAD_A
#undef LOAD_B
#undef STORE_STAGE
}

// ---------------- gi GEMM with u-finalize in A-stage ----------------
__global__ void __launch_bounds__(256, 2)
gi_kernel() {
    __shared__ float As[2][32][33];
    __shared__ float Bs[2][32][68];
    __shared__ float invZ[32];
    const int r0 = blockIdx.x * 32;
    const int o0 = blockIdx.y * 64;
    const int tid = threadIdx.x;
    const int tx = tid & 15;
    const int ty = tid >> 4;

    if (tid < 32) {
        int gr = r0 + tid, bi = gr >> 3, si = gr & 7;
        float zz = 0.f;
#pragma unroll
        for (int c = 0; c < NBLK; c++) zz += g_partZ[(bi * NBLK + c) * NS + si];
        invZ[tid] = 1.f / zz;
    }
    __syncthreads();

    float4 va, vb0, vb1;

#define GLOAD_A(kk)                                                                           \
    do {                                                                                      \
        int r = tid >> 3;                                                                     \
        int k4 = (tid & 7) << 2;                                                              \
        int gr = r0 + r, bi = gr >> 3, si = gr & 7;                                           \
        float4 s = *(const float4*)&g_partU[((bi * NBLK + 0) * NS + si) * Db + (kk) + k4];    \
        _Pragma("unroll") for (int c = 1; c < NBLK; c++) {                                    \
            float4 vv = *(const float4*)&g_partU[((bi * NBLK + c) * NS + si) * Db + (kk) + k4]; \
            s.x += vv.x; s.y += vv.y; s.z += vv.z; s.w += vv.w;                               \
        }                                                                                     \
        float iz = invZ[r];                                                                   \
        va.x = s.x * iz; va.y = s.y * iz; va.z = s.z * iz; va.w = s.w * iz;                   \
    } while (0)

#define GLOAD_B(kk)                                                                 \
    do {                                                                            \
        int o = tid >> 2;                                                           \
        int k4 = (tid & 3) << 3;                                                    \
        vb0 = *(const float4*)(g_wcomb + (size_t)(o0 + o) * Db + (kk) + k4);        \
        vb1 = *(const float4*)(g_wcomb + (size_t)(o0 + o) * Db + (kk) + k4 + 4);    \
    } while (0)

#define GSTORE(buf)                                                          \
    do {                                                                     \
        int r = tid >> 3;                                                    \
        int k4 = (tid & 7) << 2;                                             \
        As[buf][k4 + 0][r] = va.x; As[buf][k4 + 1][r] = va.y;                \
        As[buf][k4 + 2][r] = va.z; As[buf][k4 + 3][r] = va.w;                \
        int o = tid >> 2;                                                    \
        int kb = (tid & 3) << 3;                                             \
        Bs[buf][kb + 0][o] = vb0.x; Bs[buf][kb + 1][o] = vb0.y;              \
        Bs[buf][kb + 2][o] = vb0.z; Bs[buf][kb + 3][o] = vb0.w;              \
        Bs[buf][kb + 4][o] = vb1.x; Bs[buf][kb + 5][o] = vb1.y;              \
        Bs[buf][kb + 6][o] = vb1.z; Bs[buf][kb + 7][o] = vb1.w;              \
    } while (0)

    float acc[2][4];
#pragma unroll
    for (int i = 0; i < 2; i++)
#pragma unroll
        for (int j = 0; j < 4; j++) acc[i][j] = 0.f;

    GLOAD_A(0);
    GLOAD_B(0);
    GSTORE(0);
    __syncthreads();

    int cur = 0;
    for (int kki = 0; kki < 8; kki++) {
        if (kki + 1 < 8) {
            GLOAD_A((kki + 1) << 5);
            GLOAD_B((kki + 1) << 5);
        }
#pragma unroll
        for (int k = 0; k < 32; k++) {
            float a0 = As[cur][k][ty * 2 + 0];
            float a1 = As[cur][k][ty * 2 + 1];
            float4 b4 = *(const float4*)&Bs[cur][k][tx << 2];
            acc[0][0] = fmaf(a0, b4.x, acc[0][0]); acc[0][1] = fmaf(a0, b4.y, acc[0][1]);
            acc[0][2] = fmaf(a0, b4.z, acc[0][2]); acc[0][3] = fmaf(a0, b4.w, acc[0][3]);
            acc[1][0] = fmaf(a1, b4.x, acc[1][0]); acc[1][1] = fmaf(a1, b4.y, acc[1][1]);
            acc[1][2] = fmaf(a1, b4.z, acc[1][2]); acc[1][3] = fmaf(a1, b4.w, acc[1][3]);
        }
        if (kki + 1 < 8) GSTORE(cur ^ 1);
        __syncthreads();
        cur ^= 1;
    }
#pragma unroll
    for (int i = 0; i < 2; i++) {
        int r = r0 + ty * 2 + i;
        int ob = o0 + (tx << 2);
        float4 v;
        v.x = acc[i][0] + g_bcomb[ob + 0];
        v.y = acc[i][1] + g_bcomb[ob + 1];
        v.z = acc[i][2] + g_bcomb[ob + 2];
        v.w = acc[i][3] + g_bcomb[ob + 3];
        *(float4*)(g_gi + (size_t)r * (3 * Db) + ob) = v;
    }
#undef GLOAD_A
#undef GLOAD_B
#undef GSTORE
}

// ---------------- main fused pass: slot-LN+qk prologue + cp.async ring ----------------
template <int FIRST>
__global__ void __launch_bounds__(256, 1)
main_pass_kernel(const float* __restrict__ inputs, const float* __restrict__ ln_g,
                 const float* __restrict__ ln_b, const float* __restrict__ slot_g,
                 const float* __restrict__ slot_b, int reverse) {
    __shared__ float stage[8][4][Db];   // prologue: [0..2047]=sn, [2048..4095]=qk
    __shared__ float sU[NS * Db];
    __shared__ float sZ[NS];
    __shared__ float qbs[NS];

    const int batch = blockIdx.x / NBLK;
    const int chunk = blockIdx.x % NBLK;
    const int tid = threadIdx.x;
    const int w = tid >> 5, l = tid & 31;

    float* snS = &stage[0][0][0];
    float* qkS = snS + NS * Db;

    // ---- prologue A: warp w LNs slot row w, computes qb_w ----
    {
        const float4* sr = (const float4*)&g_slots[(batch * NS + w) * Db];
        float4 a = sr[l * 2], c = sr[l * 2 + 1];
        float x[8] = {a.x, a.y, a.z, a.w, c.x, c.y, c.z, c.w};
        float s = 0.f, s2 = 0.f;
#pragma unroll
        for (int k = 0; k < 8; k++) {
            s += x[k];
            s2 = fmaf(x[k], x[k], s2);
        }
#pragma unroll
        for (int o = 16; o; o >>= 1) {
            s += __shfl_xor_sync(0xffffffffu, s, o);
            s2 += __shfl_xor_sync(0xffffffffu, s2, o);
        }
        float mean = s * (1.f / Db);
        float rstd = rsqrtf(s2 * (1.f / Db) - mean * mean + EPS_LN);
        float4 ga = ((const float4*)slot_g)[l * 2], gc = ((const float4*)slot_g)[l * 2 + 1];
        float4 ba = ((const float4*)slot_b)[l * 2], bc = ((const float4*)slot_b)[l * 2 + 1];
        float gg[8] = {ga.x, ga.y, ga.z, ga.w, gc.x, gc.y, gc.z, gc.w};
        float bb[8] = {ba.x, ba.y, ba.z, ba.w, bc.x, bc.y, bc.z, bc.w};
        float4 wa = ((const float4*)g_wqbk)[l * 2], wc = ((const float4*)g_wqbk)[l * 2 + 1];
        float wq[8] = {wa.x, wa.y, wa.z, wa.w, wc.x, wc.y, wc.z, wc.w};
        float p = 0.f;
#pragma unroll
        for (int k = 0; k < 8; k++) {
            float v = (x[k] - mean) * rstd * gg[k] + bb[k];
            snS[w * Db + l * 8 + k] = v;
            p = fmaf(v, wq[k], p);
        }
#pragma unroll
        for (int o = 16; o; o >>= 1) p += __shfl_xor_sync(0xffffffffu, p, o);
        if (l == 0) qbs[w] = p + g_bqbk[0];
    }
    __syncthreads();

    // ---- prologue B: qk[i][tid] = sn[i] . Wqk[:,tid] + bqk[tid] ----
    {
        float acc[NS];
#pragma unroll
        for (int i = 0; i < NS; i++) acc[i] = g_bqk[tid];
        for (int k = 0; k < Db; k += 4) {
            float w0 = g_Wqk[(k + 0) * Db + tid];
            float w1 = g_Wqk[(k + 1) * Db + tid];
            float w2 = g_Wqk[(k + 2) * Db + tid];
            float w3 = g_Wqk[(k + 3) * Db + tid];
#pragma unroll
            for (int i = 0; i < NS; i++) {
                float4 s4 = *(const float4*)&snS[i * Db + k];
                acc[i] = fmaf(s4.x, w0, acc[i]);
                acc[i] = fmaf(s4.y, w1, acc[i]);
                acc[i] = fmaf(s4.z, w2, acc[i]);
                acc[i] = fmaf(s4.w, w3, acc[i]);
            }
        }
#pragma unroll
        for (int i = 0; i < NS; i++) qkS[i * Db + tid] = acc[i];
    }
    __syncthreads();

    float2 g2[4], b2[4];
    {
        float4 a = ((const float4*)ln_g)[l * 2];
        float4 c = ((const float4*)ln_g)[l * 2 + 1];
        float4 d = ((const float4*)ln_b)[l * 2];
        float4 e = ((const float4*)ln_b)[l * 2 + 1];
        g2[0] = make_float2(a.x, a.y); g2[1] = make_float2(a.z, a.w);
        g2[2] = make_float2(c.x, c.y); g2[3] = make_float2(c.z, c.w);
        b2[0] = make_float2(d.x, d.y); b2[1] = make_float2(d.z, d.w);
        b2[2] = make_float2(e.x, e.y); b2[3] = make_float2(e.z, e.w);
    }

    float2 qkg2[NS][4];
    float A_[NS], Bc[NS];
    {
#pragma unroll
        for (int i = 0; i < NS; i++) {
            float4 a = *(const float4*)&qkS[i * Db + l * 8];
            float4 c = *(const float4*)&qkS[i * Db + l * 8 + 4];
            float2 q2[4] = {make_float2(a.x, a.y), make_float2(a.z, a.w),
                            make_float2(c.x, c.y), make_float2(c.z, c.w)};
            float2 aL = make_float2(0.f, 0.f), bL = make_float2(0.f, 0.f);
#pragma unroll
            for (int k = 0; k < 4; k++) {
                aL = f2fma(q2[k], g2[k], aL);
                bL = f2fma(q2[k], b2[k], bL);
                qkg2[i][k] = f2mul(f2mul(q2[k], g2[k]),
                                   make_float2(ATT_SCALE, ATT_SCALE));
            }
            A_[i] = aL.x + aL.y;
            Bc[i] = bL.x + bL.y;
        }
#pragma unroll
        for (int o = 16; o; o >>= 1) {
#pragma unroll
            for (int i = 0; i < NS; i++) {
                A_[i] += __shfl_xor_sync(0xffffffffu, A_[i], o);
                Bc[i] += __shfl_xor_sync(0xffffffffu, Bc[i], o);
            }
        }
#pragma unroll
        for (int i = 0; i < NS; i++) {
            A_[i] *= ATT_SCALE;
            Bc[i] = (Bc[i] + qbs[i]) * ATT_SCALE;
        }
    }
    __syncthreads();

    float2 U2[NS][4];
    float Z[NS];
#pragma unroll
    for (int i = 0; i < NS; i++) {
        Z[i] = 0.f;
#pragma unroll
        for (int k = 0; k < 4; k++) U2[i][k] = make_float2(0.f, 0.f);
    }

    const int TPW = NTOK / NBLK / 8;  // 128
    const int base = chunk * (NTOK / NBLK) + w * TPW;
    const float* src_base = inputs + (size_t)batch * NTOK * Db + l * 8;
    uint32_t st_base;
    {
        void* p = &stage[w][0][l * 8];
        st_base = (uint32_t)__cvta_generic_to_shared(p);
    }

#pragma unroll
    for (int j = 0; j < 3; j++) {
        int tok = reverse ? (base + TPW - 1 - j) : (base + j);
        const float* s = src_base + (size_t)tok * Db;
        uint32_t d = st_base + (uint32_t)(j * Db * 4);
        cp16(d, s);
        cp16(d + 16, s + 4);
        asm volatile("cp.async.commit_group;" ::: "memory");
    }

    float2 mrc;
    if (!FIRST) {
        int tok0 = reverse ? (base + TPW - 1) : base;
        mrc = g_mr[batch * NTOK + tok0];
    }

#pragma unroll 1
    for (int tt = 0; tt < TPW; tt += 4) {
#pragma unroll
        for (int jj = 0; jj < 4; jj++) {
            int t = tt + jj;
            int tok_cur = reverse ? (base + TPW - 1 - t) : (base + t);
            asm volatile("cp.async.wait_group 2;" ::: "memory");
            float4 xa = *(const float4*)&stage[w][jj][l * 8];
            float4 xc = *(const float4*)&stage[w][jj][l * 8 + 4];
            int ft = t + 3;
            if (ft < TPW) {
                int tok = reverse ? (base + TPW - 1 - ft) : (base + ft);
                const float* s = src_base + (size_t)tok * Db;
                uint32_t d = st_base + (uint32_t)((((jj + 3) & 3) * Db) * 4);
                cp16(d, s);
                cp16(d + 16, s + 4);
            }
            asm volatile("cp.async.commit_group;" ::: "memory");

            float2 x2[4];
            x2[0] = make_float2(xa.x, xa.y); x2[1] = make_float2(xa.z, xa.w);
            x2[2] = make_float2(xc.x, xc.y); x2[3] = make_float2(xc.z, xc.w);

            float mean, rstd;
            float2 mr_next;
            if (!FIRST) {
                mean = mrc.x;
                rstd = mrc.y;
                if (t + 1 < TPW) {
                    int tokn = reverse ? (base + TPW - 2 - t) : (base + t + 1);
                    mr_next = g_mr[batch * NTOK + tokn];
                }
            }

            float2 pd2[NS];
#pragma unroll
            for (int i = 0; i < NS; i++) pd2[i] = make_float2(0.f, 0.f);
            float2 sv = make_float2(0.f, 0.f);
            float2 qv = make_float2(0.f, 0.f);
#pragma unroll
            for (int k = 0; k < 4; k++) {
                if (FIRST) {
                    sv = f2add(sv, x2[k]);
                    qv = f2fma(x2[k], x2[k], qv);
                }
#pragma unroll
                for (int i = 0; i < NS; i++) pd2[i] = f2fma(qkg2[i][k], x2[k], pd2[i]);
            }
            float d[NS];
#pragma unroll
            for (int i = 0; i < NS; i++) d[i] = pd2[i].x + pd2[i].y;
            if (FIRST) {
                float s = sv.x + sv.y;
                float s2 = qv.x + qv.y;
#pragma unroll
                for (int o = 16; o; o >>= 1) {
                    s += __shfl_xor_sync(0xffffffffu, s, o);
                    s2 += __shfl_xor_sync(0xffffffffu, s2, o);
#pragma unroll
                    for (int i = 0; i < NS; i++) d[i] += __shfl_xor_sync(0xffffffffu, d[i], o);
                }
                mean = s * (1.f / Db);
                rstd = rsqrtf(s2 * (1.f / Db) - mean * mean + EPS_LN);
                if (l == 0) g_mr[batch * NTOK + tok_cur] = make_float2(mean, rstd);
            } else {
#pragma unroll
                for (int o = 16; o; o >>= 1) {
#pragma unroll
                    for (int i = 0; i < NS; i++) d[i] += __shfl_xor_sync(0xffffffffu, d[i], o);
                }
            }
            float mr = -mean * rstd;
            // softmax without max-subtraction: logits are O(1), no overflow risk
            float p[NS], se = 0.f;
#pragma unroll
            for (int i = 0; i < NS; i++) {
                p[i] = __expf(fmaf(rstd, d[i], fmaf(mr, A_[i], Bc[i])));
                se += p[i];
            }
            float inv = __fdividef(1.f, se);
            float2 rstd2 = make_float2(rstd, rstd);
            float2 nm2 = make_float2(mr, mr);
            float2 xn2[4];
#pragma unroll
            for (int k = 0; k < 4; k++) {
                float2 w2 = f2mul(g2[k], rstd2);
                float2 c2 = f2fma(nm2, g2[k], b2[k]);
                xn2[k] = f2fma(x2[k], w2, c2);
            }
#pragma unroll
            for (int i = 0; i < NS; i++) {
                float pi = fmaf(p[i], inv, EPS_ATTN);
                Z[i] += pi;
                float2 pp = make_float2(pi, pi);
#pragma unroll
                for (int k = 0; k < 4; k++) U2[i][k] = f2fma(pp, xn2[k], U2[i][k]);
            }
            if (!FIRST) mrc = mr_next;
        }
    }

    for (int ww = 0; ww < 8; ww++) {
        if (w == ww) {
#pragma unroll
            for (int i = 0; i < NS; i++) {
#pragma unroll
                for (int k = 0; k < 4; k++) {
                    int idx = i * Db + l * 8 + 2 * k;
                    if (ww == 0) {
                        sU[idx] = U2[i][k].x;
                        sU[idx + 1] = U2[i][k].y;
                    } else {
                        sU[idx] += U2[i][k].x;
                        sU[idx + 1] += U2[i][k].y;
                    }
                }
            }
            if (l == 0) {
#pragma unroll
                for (int i = 0; i < NS; i++) {
                    if (ww == 0) sZ[i] = Z[i];
                    else sZ[i] += Z[i];
                }
            }
        }
        __syncthreads();
    }
    int outb = (batch * NBLK + chunk) * NS * Db;
    for (int idx = tid; idx < NS * Db; idx += 256) g_partU[outb + idx] = sU[idx];
    if (tid < NS) g_partZ[(batch * NBLK + chunk) * NS + tid] = sZ[tid];
}

// ---------------- GRU elementwise + LN(mlp) fused ----------------
__global__ void gru_ln_kernel(const float* __restrict__ g, const float* __restrict__ bpar) {
    int row = blockIdx.x;
    int t = threadIdx.x;
    int w = t >> 5, l = t & 31;
    const float* gi = &g_gi[row * 3 * Db];
    const float* gh = &g_gh[row * 3 * Db];
    float h = g_slots[row * Db + t];
    float r = 1.f / (1.f + expf(-(gi[t] + gh[t])));
    float z = 1.f / (1.f + expf(-(gi[Db + t] + gh[Db + t])));
    float n = tanhf(gi[2 * Db + t] + r * gh[2 * Db + t]);
    float hn = (1.f - z) * n + z * h;
    g_slots[row * Db + t] = hn;
    __shared__ float sm[8], sm2[8], bc[2];
    float s = hn, s2 = hn * hn;
#pragma unroll
    for (int o = 16; o; o >>= 1) {
        s += __shfl_xor_sync(0xffffffffu, s, o);
        s2 += __shfl_xor_sync(0xffffffffu, s2, o);
    }
    if (l == 0) { sm[w] = s; sm2[w] = s2; }
    __syncthreads();
    if (t == 0) {
        float a = 0.f, a2 = 0.f;
#pragma unroll
        for (int i = 0; i < 8; i++) { a += sm[i]; a2 += sm2[i]; }
        float m = a * (1.f / Db);
        bc[0] = m;
        bc[1] = rsqrtf(a2 * (1.f / Db) - m * m + EPS_LN);
    }
    __syncthreads();
    g_hn[row * Db + t] = (hn - bc[0]) * bc[1] * g[t] + bpar[t];
}

// ---------------- launch ----------------
extern "C" void kernel_launch(void* const* d_in, const int* in_sizes, int n_in,
                              void* d_out, int out_size) {
    const float* inputs = (const float*)d_in[0];
    const float* slots = (const float*)d_in[1];
    const float* ln_in_g = (const float*)d_in[3];
    const float* ln_in_b = (const float*)d_in[4];
    const float* ln_slot_g = (const float*)d_in[5];
    const float* ln_slot_b = (const float*)d_in[6];
    const float* ln_mlp_g = (const float*)d_in[7];
    const float* ln_mlp_b = (const float*)d_in[8];
    const float* Wq = (const float*)d_in[9];
    const float* bq = (const float*)d_in[10];
    const float* Wk = (const float*)d_in[11];
    const float* bk = (const float*)d_in[12];
    const float* Wv = (const float*)d_in[13];
    const float* bv = (const float*)d_in[14];
    const float* W_ih = (const float*)d_in[15];
    const float* b_ih = (const float*)d_in[16];
    const float* W_hh = (const float*)d_in[17];
    const float* b_hh = (const float*)d_in[18];
    const float* W1 = (const float*)d_in[19];
    const float* b1 = (const float*)d_in[20];
    const float* W2 = (const float*)d_in[21];
    const float* b2 = (const float*)d_in[22];
    float* out = (float*)d_out;

    float *p_hn, *p_m1, *p_slots, *p_Wqk, *p_wcomb, *p_gh;
    cudaGetSymbolAddress((void**)&p_hn, g_hn);
    cudaGetSymbolAddress((void**)&p_m1, g_m1);
    cudaGetSymbolAddress((void**)&p_slots, g_slots);
    cudaGetSymbolAddress((void**)&p_Wqk, g_Wqk);
    cudaGetSymbolAddress((void**)&p_wcomb, g_wcomb);
    cudaGetSymbolAddress((void**)&p_gh, g_gh);

    // side stream + fork/join events (host objects, created once; same captured
    // work on every call)
    static cudaStream_t s2 = nullptr;
    static cudaEvent_t eF[3], eJ[3];
    if (!s2) {
        cudaStreamCreateWithFlags(&s2, cudaStreamNonBlocking);
        for (int i = 0; i < 3; i++) {
            cudaEventCreateWithFlags(&eF[i], cudaEventDisableTiming);
            cudaEventCreateWithFlags(&eJ[i], cudaEventDisableTiming);
        }
    }

    // prep (stream 0)
    prep_all_kernel<<<5 + ROWS * Db / 256, 256>>>(slots, W_ih, b_ih, bv, Wq, bq, bk, Wk);
    gemmp_kernel<1, 0, 0><<<dim3(8, 4), 256>>>(Wq, Wk, nullptr, nullptr, p_Wqk, 256, 256, 256);

    for (int it = 0; it < 3; it++) {
        // fork: slots for this iteration are final on stream 0 here
        cudaEventRecord(eF[it], 0);
        cudaStreamWaitEvent(s2, eF[it], 0);
        if (it == 0) {
            // wcomb = W_ih @ Wv (overlapped with main)
            gemmp_kernel<0, 0, 0><<<dim3(24, 4), 256, 0, s2>>>(W_ih, Wv, nullptr, nullptr,
                                                               p_wcomb, 768, 256, 256);
        }
        // gh = slots @ W_hh^T + b_hh, overlapped with main_pass
        gemmp_kernel<0, 1, 0><<<dim3(8, 12), 256, 0, s2>>>(p_slots, W_hh, b_hh, nullptr,
                                                           p_gh, 256, 768, 256);
        cudaEventRecord(eJ[it], s2);

        // main_pass (with fused slot-LN + qk prologue) on stream 0
        if (it == 0)
            main_pass_kernel<1><<<NB * NBLK, 256>>>(inputs, ln_in_g, ln_in_b,
                                                    ln_slot_g, ln_slot_b, 0);
        else
            main_pass_kernel<0><<<NB * NBLK, 256>>>(inputs, ln_in_g, ln_in_b,
                                                    ln_slot_g, ln_slot_b, it & 1);
        // join before anything that writes g_slots or reads g_gh/g_wcomb
        cudaStreamWaitEvent(0, eJ[it], 0);
        // gi = u @ wcomb^T + bcomb
        gi_kernel<<<dim3(8, 12), 256>>>();
        gru_ln_kernel<<<ROWS, 256>>>(ln_mlp_g, ln_mlp_b);
        // m1 = relu(hn @ W1^T + b1)
        gemmp_kernel<0, 1, 1><<<dim3(8, 8), 256>>>(p_hn, W1, b1, nullptr, p_m1, 256, 512, 256);
        // slots = m1 @ W2^T + b2 + slots
        float* Cdst = (it == 2) ? out : p_slots;
        gemmp_kernel<0, 1, 0><<<dim3(8, 4), 256>>>(p_m1, W2, b2, p_slots, Cdst, 256, 256, 512);
    }
}